// round 7
// baseline (speedup 1.0000x reference)
#include <cuda_runtime.h>
#include <cuda_bf16.h>
#include <cstdint>

#define NB 4
#define NS 2048
#define ND 1024
#define NH 16
#define DKH 64
#define MROWS (NB*NS)   // 8192
#define KX2 2048        // 2 physical planes [hi | lo] per row

// ---------------- scratch (__device__ globals; no allocation) ----------------
__device__ __nv_bfloat16 g_xs[(size_t)MROWS * KX2];    // x split    [hi|lo]
__device__ __nv_bfloat16 g_as[(size_t)MROWS * KX2];    // attn split [hi|lo]
__device__ __nv_bfloat16 g_wqkv[(size_t)3 * ND * KX2]; // Wq|Wk|Wv   [hi|lo]
__device__ __nv_bfloat16 g_wo[(size_t)ND * KX2];
// split-bf16 Q/K/V: [bh][plane(hi=0,lo=1)][S][64]
__device__ __nv_bfloat16 g_q[(size_t)NB*NH*2*NS*DKH];
__device__ __nv_bfloat16 g_k[(size_t)NB*NH*2*NS*DKH];
__device__ __nv_bfloat16 g_v[(size_t)NB*NH*2*NS*DKH];

// ---------------- helpers ----------------
__device__ __forceinline__ uint32_t smem_u32(const void* p) {
    uint32_t a;
    asm("{ .reg .u64 t; cvta.to.shared.u64 t, %1; cvt.u32.u64 %0, t; }" : "=r"(a) : "l"(p));
    return a;
}
__device__ __forceinline__ void ldsm4(uint32_t* r, uint32_t addr) {
    asm volatile("ldmatrix.sync.aligned.m8n8.x4.shared.b16 {%0,%1,%2,%3}, [%4];"
                 : "=r"(r[0]), "=r"(r[1]), "=r"(r[2]), "=r"(r[3]) : "r"(addr));
}
__device__ __forceinline__ void ldsm4t(uint32_t* r, uint32_t addr) {
    asm volatile("ldmatrix.sync.aligned.m8n8.x4.trans.shared.b16 {%0,%1,%2,%3}, [%4];"
                 : "=r"(r[0]), "=r"(r[1]), "=r"(r[2]), "=r"(r[3]) : "r"(addr));
}
__device__ __forceinline__ void mma16816(float* c, const uint32_t* a, uint32_t b0, uint32_t b1) {
    asm volatile("mma.sync.aligned.m16n8k16.row.col.f32.bf16.bf16.f32 "
                 "{%0,%1,%2,%3}, {%4,%5,%6,%7}, {%8,%9}, {%0,%1,%2,%3};"
                 : "+f"(c[0]), "+f"(c[1]), "+f"(c[2]), "+f"(c[3])
                 : "r"(a[0]), "r"(a[1]), "r"(a[2]), "r"(a[3]), "r"(b0), "r"(b1));
}
__device__ __forceinline__ void cpasync16(uint32_t dst, const void* src) {
    asm volatile("cp.async.cg.shared.global [%0], [%1], 16;" :: "r"(dst), "l"(src));
}
__device__ __forceinline__ void cp_commit() {
    asm volatile("cp.async.commit_group;" ::: "memory");
}
__device__ __forceinline__ uint32_t packbf(float a, float b) {
    __nv_bfloat162 h = __floats2bfloat162_rn(a, b);
    return *(uint32_t*)&h;
}
__device__ __forceinline__ uint32_t packlo(float a, float b, uint32_t hbits) {
    __nv_bfloat162 h = *(__nv_bfloat162*)&hbits;
    return packbf(a - __bfloat162float(h.x), b - __bfloat162float(h.y));
}

// ---------------- fp32 -> split-bf16 (2 planes per row: [hi | lo]) ----------
__global__ void split_act(const float* __restrict__ src, __nv_bfloat16* __restrict__ dst)
{
    int i = blockIdx.x * blockDim.x + threadIdx.x;
    int r  = i >> 9;
    int cp = i & 511;
    float2 v = *(const float2*)(src + (size_t)r * ND + cp * 2);
    __nv_bfloat162 hh = __floats2bfloat162_rn(v.x, v.y);
    __nv_bfloat162 ll = __floats2bfloat162_rn(v.x - __bfloat162float(hh.x),
                                              v.y - __bfloat162float(hh.y));
    __nv_bfloat162* d2 = (__nv_bfloat162*)(dst + (size_t)r * KX2) + cp;
    d2[0]   = hh;
    d2[512] = ll;
}
__global__ void split_w(const float* __restrict__ Wq, const float* __restrict__ Wk,
                        const float* __restrict__ Wv, const float* __restrict__ Wo,
                        __nv_bfloat16* __restrict__ wqkv, __nv_bfloat16* __restrict__ wo)
{
    int which = blockIdx.y;
    const float* src = (which == 0) ? Wq : (which == 1) ? Wk : (which == 2) ? Wv : Wo;
    __nv_bfloat16* dst = (which == 3) ? wo : wqkv + (size_t)which * ND * KX2;
    int i = blockIdx.x * blockDim.x + threadIdx.x;
    int r  = i >> 9;
    int cp = i & 511;
    float2 v = *(const float2*)(src + (size_t)r * ND + cp * 2);
    __nv_bfloat162 hh = __floats2bfloat162_rn(v.x, v.y);
    __nv_bfloat162 ll = __floats2bfloat162_rn(v.x - __bfloat162float(hh.x),
                                              v.y - __bfloat162float(hh.y));
    __nv_bfloat162* d2 = (__nv_bfloat162*)(dst + (size_t)r * KX2) + cp;
    d2[0]   = hh;
    d2[512] = ll;
}

// ---------------- HMMA split-bf16 NT GEMM (3-term, 2-plane) -----------------
// C = Ah*Bh^T + Al*Bh^T + Ah*Bl^T over true K=1024. CTA 128x128, BK=32,
// 128 thr = 4 warps (2m x 2n, 64x64 warp tiles), 3-stage cp.async.
// Stage = 4 tiles (Ah,Al,Bh,Bl) of 128x32 bf16 (8KB each, 64B rows, SW64 swz).
static constexpr int GEMM_NT   = 1024 / 32;  // 32 stages
static constexpr int STAGE_B   = 4 * 8192;   // 32768
static constexpr int GEMM_SMEM = 3 * STAGE_B;

__device__ __forceinline__ uint32_t swz64(uint32_t off) {
    return off ^ ((off >> 3) & 0x30);
}

__device__ __forceinline__ void gemm_cp(const __nv_bfloat16* __restrict__ A,
                                        const __nv_bfloat16* __restrict__ Bw,
                                        int m0, int n0, int k0,
                                        uint32_t sbuf, int tid)
{
    #pragma unroll
    for (int i = 0; i < 16; i++) {
        int c = tid + i * 128;            // 0..2047 16B chunks
        int tile = c >> 9;                // 0:Ah 1:Al 2:Bh 3:Bl
        int cc = c & 511;
        int r = cc >> 2, col16 = cc & 3;
        const __nv_bfloat16* src = (tile < 2)
            ? A  + (size_t)(m0 + r) * KX2 + (tile & 1) * 1024 + k0 + col16 * 8
            : Bw + (size_t)(n0 + r) * KX2 + (tile & 1) * 1024 + k0 + col16 * 8;
        uint32_t off = (uint32_t)(r * 64 + col16 * 16);
        cpasync16(sbuf + tile * 8192u + swz64(off), src);
    }
}

template<int OMODE>   // 0: fp32 out [M,ND]; 1: merged QKV -> split head layout
__global__ void __launch_bounds__(128, 2)
gemm_mma(const __nv_bfloat16* __restrict__ A, const __nv_bfloat16* __restrict__ Bw,
         float* __restrict__ outF,
         __nv_bfloat16* __restrict__ qp, __nv_bfloat16* __restrict__ kp,
         __nv_bfloat16* __restrict__ vp)
{
    extern __shared__ __align__(1024) char smem[];
    const int tid  = threadIdx.x;
    const int lane = tid & 31;
    const int wid  = tid >> 5;
    const int warp_m = wid & 1;    // 2 x 64 rows
    const int warp_n = wid >> 1;   // 2 x 64 cols
    const int m0 = blockIdx.y * 128;
    const int n0 = blockIdx.x * 128;

    const uint32_t sbase = smem_u32(smem);
    const int qrow = lane & 15;
    const int qcol = lane >> 4;

    float acc[4][8][4];
    #pragma unroll
    for (int a = 0; a < 4; a++)
        #pragma unroll
        for (int b = 0; b < 8; b++)
            #pragma unroll
            for (int c = 0; c < 4; c++) acc[a][b][c] = 0.f;

    gemm_cp(A, Bw, m0, n0, 0,  sbase,                     tid); cp_commit();
    gemm_cp(A, Bw, m0, n0, 32, sbase + (uint32_t)STAGE_B, tid); cp_commit();

    int buf_c = 0;
    int buf_i = 2;
    #pragma unroll 1
    for (int t = 0; t < GEMM_NT; t++) {
        asm volatile("cp.async.wait_group 1;" ::: "memory");
        __syncthreads();
        if (t + 2 < GEMM_NT)
            gemm_cp(A, Bw, m0, n0, (t + 2) * 32,
                    sbase + (uint32_t)buf_i * STAGE_B, tid);
        cp_commit();

        const uint32_t sAh = sbase + (uint32_t)buf_c * STAGE_B;
        const uint32_t sAl = sAh + 8192u;
        const uint32_t sBh = sAh + 16384u;
        const uint32_t sBl = sAh + 24576u;

        #pragma unroll
        for (int ks = 0; ks < 2; ks++) {
            uint32_t ah[4][4], al[4][4], bh[4][4], bl[4][4];
            #pragma unroll
            for (int mi = 0; mi < 4; mi++) {
                uint32_t off = (uint32_t)((warp_m * 64 + mi * 16 + qrow) * 64
                                          + (ks * 2 + qcol) * 16);
                off = swz64(off);
                ldsm4(ah[mi], sAh + off);
                ldsm4(al[mi], sAl + off);
            }
            #pragma unroll
            for (int nj = 0; nj < 4; nj++) {
                uint32_t off = (uint32_t)((warp_n * 64 + nj * 16 + qrow) * 64
                                          + (ks * 2 + qcol) * 16);
                off = swz64(off);
                ldsm4(bh[nj], sBh + off);
                ldsm4(bl[nj], sBl + off);
            }
            #pragma unroll
            for (int mi = 0; mi < 4; mi++)
                #pragma unroll
                for (int ni = 0; ni < 8; ni++) {
                    uint32_t h0 = bh[ni >> 1][ni & 1], h1 = bh[ni >> 1][2 + (ni & 1)];
                    uint32_t l0 = bl[ni >> 1][ni & 1], l1 = bl[ni >> 1][2 + (ni & 1)];
                    mma16816(acc[mi][ni], ah[mi], h0, h1);
                    mma16816(acc[mi][ni], al[mi], h0, h1);
                    mma16816(acc[mi][ni], ah[mi], l0, l1);
                }
        }

        buf_c = (buf_c == 2) ? 0 : buf_c + 1;
        buf_i = (buf_i == 2) ? 0 : buf_i + 1;
        __syncthreads();
    }

    const int tr = lane >> 2;
    const int tc = (lane & 3) * 2;
    const int which = n0 >> 10;                 // 0:Q 1:K 2:V (OMODE 1)
    const float scale = (OMODE == 1 && which == 0) ? 0.125f : 1.f;
    __nv_bfloat16* hdst = (which == 0) ? qp : (which == 1) ? kp : vp;
    const int ncol0 = n0 & 1023;

    #pragma unroll
    for (int mi = 0; mi < 4; mi++) {
        #pragma unroll
        for (int ni = 0; ni < 8; ni++) {
            const int row = m0 + warp_m * 64 + mi * 16 + tr;
            const int col = (OMODE ? ncol0 : n0) + warp_n * 64 + ni * 8 + tc;
            float* cc = acc[mi][ni];
            #pragma unroll
            for (int half = 0; half < 2; half++) {
                const int r = row + half * 8;
                float2 val = half ? make_float2(cc[2], cc[3]) : make_float2(cc[0], cc[1]);
                if (OMODE == 0) {
                    *(float2*)(outF + (size_t)r * ND + col) = val;
                } else {
                    val.x *= scale; val.y *= scale;
                    const int b = r >> 11, s = r & (NS - 1);
                    const int h = col >> 6, ch = col & 63;
                    __nv_bfloat162 hi = __floats2bfloat162_rn(val.x, val.y);
                    __nv_bfloat162 lo = __floats2bfloat162_rn(
                        val.x - __bfloat162float(hi.x), val.y - __bfloat162float(hi.y));
                    __nv_bfloat16* base = hdst
                        + (((size_t)(b * NH + h) * 2) * NS + s) * 64 + ch;
                    *(__nv_bfloat162*)base           = hi;
                    *(__nv_bfloat162*)(base + NS*64) = lo;
                }
            }
        }
    }
}

// ---------------------------------------------------------------------------
// HMMA causal flash attention (unchanged core). CTA = (bh, 128 q-rows).
// Epilogue writes the 2-plane [hi | lo] A-operand rows for the Wo GEMM.
// ---------------------------------------------------------------------------
static constexpr int ATTN_SMEM = 32768 + 2 * 32768;  // 98304

__global__ void __launch_bounds__(128)
fattn(const __nv_bfloat16* __restrict__ Qg, const __nv_bfloat16* __restrict__ Kg,
      const __nv_bfloat16* __restrict__ Vg, __nv_bfloat16* __restrict__ As)
{
    extern __shared__ __align__(1024) char sm[];
    const uint32_t sb = smem_u32(sm);
    const int bh  = blockIdx.x;
    const int qt  = (int)gridDim.y - 1 - (int)blockIdx.y;
    const int tid = threadIdx.x, lane = tid & 31, w = tid >> 5;

    const __nv_bfloat16* Qbh = Qg + (size_t)bh * 2 * NS * 64;
    const __nv_bfloat16* Kbh = Kg + (size_t)bh * 2 * NS * 64;
    const __nv_bfloat16* Vbh = Vg + (size_t)bh * 2 * NS * 64;

    #pragma unroll
    for (int i = 0; i < 16; i++) {
        int c = tid + i * 128;
        int p = c >> 10, r = (c >> 3) & 127, col16 = c & 7;
        uint4 v = *(const uint4*)(Qbh + (size_t)p * NS * 64
                                  + (size_t)(qt * 128 + r) * 64 + col16 * 8);
        uint32_t off = (uint32_t)(r * 128 + col16 * 16);
        *(uint4*)(sm + p * 16384 + (off ^ ((off >> 3) & 0x70))) = v;
    }

    const int nkt = 2 * qt + 2;

    auto load_kv = [&](int kt, int buf) {
        const int kv0 = kt * 64;
        #pragma unroll
        for (int i = 0; i < 16; i++) {
            int c = tid + i * 128;
            int p = c >> 9;
            int r = (c >> 3) & 63, col16 = c & 7;
            const __nv_bfloat16* src = (p < 2 ? Kbh : Vbh)
                + (size_t)(p & 1) * NS * 64 + (size_t)(kv0 + r) * 64 + col16 * 8;
            uint32_t off = (uint32_t)(r * 128 + col16 * 16);
            cpasync16(sb + 32768 + buf * 32768 + p * 8192 + (off ^ ((off >> 3) & 0x70)), src);
        }
        cp_commit();
    };

    load_kv(0, 0);

    float m[2][2], l[2][2];
    #pragma unroll
    for (int a = 0; a < 2; a++)
        #pragma unroll
        for (int b = 0; b < 2; b++) { m[a][b] = -1e30f; l[a][b] = 0.f; }

    float o[2][8][4];
    #pragma unroll
    for (int a = 0; a < 2; a++)
        #pragma unroll
        for (int b = 0; b < 8; b++)
            #pragma unroll
            for (int c = 0; c < 4; c++) o[a][b][c] = 0.f;

    const int qw0 = qt * 128 + w * 32;
    const uint32_t qoff[3] = {0u, 16384u, 0u};
    const uint32_t koff[3] = {0u, 0u, 8192u};

    for (int kt = 0; kt < nkt; kt++) {
        if (kt + 1 < nkt) {
            load_kv(kt + 1, (kt + 1) & 1);
            asm volatile("cp.async.wait_group 1;" ::: "memory");
        } else {
            asm volatile("cp.async.wait_group 0;" ::: "memory");
        }
        __syncthreads();

        if (kt * 64 <= qw0 + 31) {
            const uint32_t sK = sb + 32768 + (uint32_t)(kt & 1) * 32768u;
            const uint32_t sV = sK + 16384u;

            float s_[2][8][4];
            #pragma unroll
            for (int a = 0; a < 2; a++)
                #pragma unroll
                for (int b = 0; b < 8; b++)
                    #pragma unroll
                    for (int c = 0; c < 4; c++) s_[a][b][c] = 0.f;

            #pragma unroll
            for (int ps = 0; ps < 3; ps++) {
                #pragma unroll
                for (int ks = 0; ks < 4; ks++) {
                    uint32_t a[2][4];
                    #pragma unroll
                    for (int mi = 0; mi < 2; mi++) {
                        uint32_t off = (uint32_t)((w * 32 + mi * 16 + (lane & 15)) * 128
                                                  + (ks * 2 + (lane >> 4)) * 16);
                        ldsm4(a[mi], sb + qoff[ps] + (off ^ ((off >> 3) & 0x70)));
                    }
                    uint32_t bb[4][4];
                    #pragma unroll
                    for (int nj = 0; nj < 4; nj++) {
                        uint32_t off = (uint32_t)((nj * 16 + (lane & 15)) * 128
                                                  + (ks * 2 + (lane >> 4)) * 16);
                        ldsm4(bb[nj], sK + koff[ps] + (off ^ ((off >> 3) & 0x70)));
                    }
                    #pragma unroll
                    for (int mi = 0; mi < 2; mi++)
                        #pragma unroll
                        for (int ni = 0; ni < 8; ni++)
                            mma16816(s_[mi][ni], a[mi],
                                     bb[ni >> 1][ni & 1], bb[ni >> 1][2 + (ni & 1)]);
                }
            }

            if (kt * 64 + 63 > qw0) {
                #pragma unroll
                for (int mi = 0; mi < 2; mi++)
                    #pragma unroll
                    for (int ni = 0; ni < 8; ni++)
                        #pragma unroll
                        for (int c = 0; c < 4; c++) {
                            int qr = qw0 + mi * 16 + ((c >> 1) << 3) + (lane >> 2);
                            int kc = kt * 64 + ni * 8 + ((lane & 3) << 1) + (c & 1);
                            if (kc > qr) s_[mi][ni][c] = -1e30f;
                        }
            }

            #pragma unroll
            for (int mi = 0; mi < 2; mi++)
                #pragma unroll
                for (int rh = 0; rh < 2; rh++) {
                    float mx = -1e30f;
                    #pragma unroll
                    for (int ni = 0; ni < 8; ni++)
                        mx = fmaxf(mx, fmaxf(s_[mi][ni][rh*2], s_[mi][ni][rh*2+1]));
                    mx = fmaxf(mx, __shfl_xor_sync(0xffffffffu, mx, 1));
                    mx = fmaxf(mx, __shfl_xor_sync(0xffffffffu, mx, 2));
                    float mn = fmaxf(m[mi][rh], mx);
                    float sc = __expf(m[mi][rh] - mn);
                    m[mi][rh] = mn;
                    float sum = 0.f;
                    #pragma unroll
                    for (int ni = 0; ni < 8; ni++) {
                        float p0 = __expf(s_[mi][ni][rh*2]   - mn);
                        float p1 = __expf(s_[mi][ni][rh*2+1] - mn);
                        s_[mi][ni][rh*2] = p0; s_[mi][ni][rh*2+1] = p1;
                        sum += p0 + p1;
                    }
                    sum += __shfl_xor_sync(0xffffffffu, sum, 1);
                    sum += __shfl_xor_sync(0xffffffffu, sum, 2);
                    l[mi][rh] = l[mi][rh] * sc + sum;
                    #pragma unroll
                    for (int ni = 0; ni < 8; ni++) {
                        o[mi][ni][rh*2]   *= sc;
                        o[mi][ni][rh*2+1] *= sc;
                    }
                }

            #pragma unroll
            for (int ks = 0; ks < 4; ks++) {
                uint32_t ah[2][4], al[2][4];
                #pragma unroll
                for (int mi = 0; mi < 2; mi++) {
                    const float* t0 = s_[mi][2*ks];
                    const float* t1 = s_[mi][2*ks+1];
                    ah[mi][0] = packbf(t0[0], t0[1]);
                    ah[mi][1] = packbf(t0[2], t0[3]);
                    ah[mi][2] = packbf(t1[0], t1[1]);
                    ah[mi][3] = packbf(t1[2], t1[3]);
                    al[mi][0] = packlo(t0[0], t0[1], ah[mi][0]);
                    al[mi][1] = packlo(t0[2], t0[3], ah[mi][1]);
                    al[mi][2] = packlo(t1[0], t1[1], ah[mi][2]);
                    al[mi][3] = packlo(t1[2], t1[3], ah[mi][3]);
                }
                uint32_t bvh[4][4], bvl[4][4];
                #pragma unroll
                for (int nj = 0; nj < 4; nj++) {
                    uint32_t off = (uint32_t)((ks * 16 + (lane & 15)) * 128
                                              + (nj * 2 + (lane >> 4)) * 16);
                    off ^= (off >> 3) & 0x70;
                    ldsm4t(bvh[nj], sV + off);
                    ldsm4t(bvl[nj], sV + 8192 + off);
                }
                #pragma unroll
                for (int mi = 0; mi < 2; mi++)
                    #pragma unroll
                    for (int nd = 0; nd < 8; nd++) {
                        uint32_t b0 = bvh[nd >> 1][(nd & 1) * 2];
                        uint32_t b1 = bvh[nd >> 1][(nd & 1) * 2 + 1];
                        mma16816(o[mi][nd], ah[mi], b0, b1);
                        mma16816(o[mi][nd], al[mi], b0, b1);
                        uint32_t c0 = bvl[nd >> 1][(nd & 1) * 2];
                        uint32_t c1 = bvl[nd >> 1][(nd & 1) * 2 + 1];
                        mma16816(o[mi][nd], ah[mi], c0, c1);
                    }
            }
        }
        __syncthreads();
    }

    // epilogue: O/l -> 2-plane split rows [hi | lo] of Wo GEMM's A operand
    const int b = bh >> 4, h = bh & 15;
    #pragma unroll
    for (int mi = 0; mi < 2; mi++)
        #pragma unroll
        for (int rh = 0; rh < 2; rh++) {
            float invl = 1.f / l[mi][rh];
            int row = qw0 + mi * 16 + rh * 8 + (lane >> 2);
            __nv_bfloat16* rbase = As + (size_t)(b * NS + row) * KX2 + h * 64;
            #pragma unroll
            for (int ni = 0; ni < 8; ni++) {
                float vx = o[mi][ni][rh*2] * invl;
                float vy = o[mi][ni][rh*2+1] * invl;
                __nv_bfloat162 hi = __floats2bfloat162_rn(vx, vy);
                __nv_bfloat162 lo = __floats2bfloat162_rn(
                    vx - __bfloat162float(hi.x), vy - __bfloat162float(hi.y));
                __nv_bfloat16* dst = rbase + ni * 8 + ((lane & 3) << 1);
                *(__nv_bfloat162*)dst          = hi;
                *(__nv_bfloat162*)(dst + 1024) = lo;
            }
        }
}

// ---------------------------------------------------------------------------
extern "C" void kernel_launch(void* const* d_in, const int* in_sizes, int n_in,
                              void* d_out, int out_size)
{
    const float* x  = (const float*)d_in[0];
    const float* Wq = (const float*)d_in[1];
    const float* Wk = (const float*)d_in[2];
    const float* Wv = (const float*)d_in[3];
    const float* Wo = (const float*)d_in[4];
    float* out = (float*)d_out;

    __nv_bfloat16 *xs, *as, *wqkv, *wo, *q, *k, *v;
    cudaGetSymbolAddress((void**)&xs,   g_xs);
    cudaGetSymbolAddress((void**)&as,   g_as);
    cudaGetSymbolAddress((void**)&wqkv, g_wqkv);
    cudaGetSymbolAddress((void**)&wo,   g_wo);
    cudaGetSymbolAddress((void**)&q,    g_q);
    cudaGetSymbolAddress((void**)&k,    g_k);
    cudaGetSymbolAddress((void**)&v,    g_v);

    cudaFuncSetAttribute(gemm_mma<0>, cudaFuncAttributeMaxDynamicSharedMemorySize, GEMM_SMEM);
    cudaFuncSetAttribute(gemm_mma<1>, cudaFuncAttributeMaxDynamicSharedMemorySize, GEMM_SMEM);
    cudaFuncSetAttribute(fattn, cudaFuncAttributeMaxDynamicSharedMemorySize, ATTN_SMEM);

    split_act<<<MROWS * (ND/2) / 256, 256>>>(x, xs);
    split_w<<<dim3(ND * (ND/2) / 256, 4), 256>>>(Wq, Wk, Wv, Wo, wqkv, wo);

    // fused QKV projection: N = 3072
    gemm_mma<1><<<dim3(3 * ND / 128, MROWS / 128), 128, GEMM_SMEM>>>(
        xs, wqkv, nullptr, q, k, v);

    fattn<<<dim3(NB * NH, NS / 128), 128, ATTN_SMEM>>>(q, k, v, as);

    gemm_mma<0><<<dim3(ND / 128, MROWS / 128), 128, GEMM_SMEM>>>(
        as, wo, out, nullptr, nullptr, nullptr);
}

// round 8
// speedup vs baseline: 1.0227x; 1.0227x over previous
#include <cuda_runtime.h>
#include <cuda_bf16.h>
#include <cstdint>

#define NB 4
#define NS 2048
#define ND 1024
#define NH 16
#define DKH 64
#define MROWS (NB*NS)   // 8192
#define KX2 2048        // 2 physical planes [hi | lo] per row

// ---------------- scratch (__device__ globals; no allocation) ----------------
__device__ __nv_bfloat16 g_xs[(size_t)MROWS * KX2];    // x split    [hi|lo]
__device__ __nv_bfloat16 g_as[(size_t)MROWS * KX2];    // attn split [hi|lo]
__device__ __nv_bfloat16 g_wqkv[(size_t)3 * ND * KX2]; // Wq|Wk|Wv   [hi|lo]
__device__ __nv_bfloat16 g_wo[(size_t)ND * KX2];
// split-bf16 Q/K/V: [bh][plane(hi=0,lo=1)][S][64]
__device__ __nv_bfloat16 g_q[(size_t)NB*NH*2*NS*DKH];
__device__ __nv_bfloat16 g_k[(size_t)NB*NH*2*NS*DKH];
__device__ __nv_bfloat16 g_v[(size_t)NB*NH*2*NS*DKH];

// ---------------- helpers ----------------
__device__ __forceinline__ uint32_t smem_u32(const void* p) {
    uint32_t a;
    asm("{ .reg .u64 t; cvta.to.shared.u64 t, %1; cvt.u32.u64 %0, t; }" : "=r"(a) : "l"(p));
    return a;
}
__device__ __forceinline__ void ldsm4(uint32_t* r, uint32_t addr) {
    asm volatile("ldmatrix.sync.aligned.m8n8.x4.shared.b16 {%0,%1,%2,%3}, [%4];"
                 : "=r"(r[0]), "=r"(r[1]), "=r"(r[2]), "=r"(r[3]) : "r"(addr));
}
__device__ __forceinline__ void ldsm4t(uint32_t* r, uint32_t addr) {
    asm volatile("ldmatrix.sync.aligned.m8n8.x4.trans.shared.b16 {%0,%1,%2,%3}, [%4];"
                 : "=r"(r[0]), "=r"(r[1]), "=r"(r[2]), "=r"(r[3]) : "r"(addr));
}
__device__ __forceinline__ void mma16816(float* c, const uint32_t* a, uint32_t b0, uint32_t b1) {
    asm volatile("mma.sync.aligned.m16n8k16.row.col.f32.bf16.bf16.f32 "
                 "{%0,%1,%2,%3}, {%4,%5,%6,%7}, {%8,%9}, {%0,%1,%2,%3};"
                 : "+f"(c[0]), "+f"(c[1]), "+f"(c[2]), "+f"(c[3])
                 : "r"(a[0]), "r"(a[1]), "r"(a[2]), "r"(a[3]), "r"(b0), "r"(b1));
}
__device__ __forceinline__ void cpasync16(uint32_t dst, const void* src) {
    asm volatile("cp.async.cg.shared.global [%0], [%1], 16;" :: "r"(dst), "l"(src));
}
__device__ __forceinline__ void cp_commit() {
    asm volatile("cp.async.commit_group;" ::: "memory");
}
__device__ __forceinline__ uint32_t packbf(float a, float b) {
    __nv_bfloat162 h = __floats2bfloat162_rn(a, b);
    return *(uint32_t*)&h;
}
__device__ __forceinline__ uint32_t packlo(float a, float b, uint32_t hbits) {
    __nv_bfloat162 h = *(__nv_bfloat162*)&hbits;
    return packbf(a - __bfloat162float(h.x), b - __bfloat162float(h.y));
}

// ---------------- fp32 -> split-bf16 (2 planes per row: [hi | lo]) ----------
__global__ void split_act(const float* __restrict__ src, __nv_bfloat16* __restrict__ dst)
{
    int i = blockIdx.x * blockDim.x + threadIdx.x;
    int r  = i >> 9;
    int cp = i & 511;
    float2 v = *(const float2*)(src + (size_t)r * ND + cp * 2);
    __nv_bfloat162 hh = __floats2bfloat162_rn(v.x, v.y);
    __nv_bfloat162 ll = __floats2bfloat162_rn(v.x - __bfloat162float(hh.x),
                                              v.y - __bfloat162float(hh.y));
    __nv_bfloat162* d2 = (__nv_bfloat162*)(dst + (size_t)r * KX2) + cp;
    d2[0]   = hh;
    d2[512] = ll;
}
__global__ void split_w(const float* __restrict__ Wq, const float* __restrict__ Wk,
                        const float* __restrict__ Wv, const float* __restrict__ Wo,
                        __nv_bfloat16* __restrict__ wqkv, __nv_bfloat16* __restrict__ wo)
{
    int which = blockIdx.y;
    const float* src = (which == 0) ? Wq : (which == 1) ? Wk : (which == 2) ? Wv : Wo;
    __nv_bfloat16* dst = (which == 3) ? wo : wqkv + (size_t)which * ND * KX2;
    int i = blockIdx.x * blockDim.x + threadIdx.x;
    int r  = i >> 9;
    int cp = i & 511;
    float2 v = *(const float2*)(src + (size_t)r * ND + cp * 2);
    __nv_bfloat162 hh = __floats2bfloat162_rn(v.x, v.y);
    __nv_bfloat162 ll = __floats2bfloat162_rn(v.x - __bfloat162float(hh.x),
                                              v.y - __bfloat162float(hh.y));
    __nv_bfloat162* d2 = (__nv_bfloat162*)(dst + (size_t)r * KX2) + cp;
    d2[0]   = hh;
    d2[512] = ll;
}

// ---------------- HMMA split-bf16 NT GEMM (3-term, 2-plane) -----------------
// C = Ah*Bh^T + Al*Bh^T + Ah*Bl^T over true K=1024. CTA 128x128, BK=32,
// 256 thr = 8 warps (2m x 4n, 64x32 warp tiles), 3-stage cp.async.
// Stage = 4 tiles (Ah,Al,Bh,Bl) of 128x32 bf16 (8KB each, 64B rows, SW64 swz).
static constexpr int GEMM_NT   = 1024 / 32;  // 32 stages
static constexpr int STAGE_B   = 4 * 8192;   // 32768
static constexpr int GEMM_SMEM = 3 * STAGE_B;

__device__ __forceinline__ uint32_t swz64(uint32_t off) {
    return off ^ ((off >> 3) & 0x30);
}

__device__ __forceinline__ void gemm_cp(const __nv_bfloat16* __restrict__ A,
                                        const __nv_bfloat16* __restrict__ Bw,
                                        int m0, int n0, int k0,
                                        uint32_t sbuf, int tid)
{
    #pragma unroll
    for (int i = 0; i < 8; i++) {
        int c = tid + i * 256;            // 0..2047 16B chunks
        int tile = c >> 9;                // 0:Ah 1:Al 2:Bh 3:Bl
        int cc = c & 511;
        int r = cc >> 2, col16 = cc & 3;
        const __nv_bfloat16* src = (tile < 2)
            ? A  + (size_t)(m0 + r) * KX2 + (tile & 1) * 1024 + k0 + col16 * 8
            : Bw + (size_t)(n0 + r) * KX2 + (tile & 1) * 1024 + k0 + col16 * 8;
        uint32_t off = (uint32_t)(r * 64 + col16 * 16);
        cpasync16(sbuf + tile * 8192u + swz64(off), src);
    }
}

template<int OMODE>   // 0: fp32 out [M,ND]; 1: merged QKV -> split head layout
__global__ void __launch_bounds__(256, 2)
gemm_mma(const __nv_bfloat16* __restrict__ A, const __nv_bfloat16* __restrict__ Bw,
         float* __restrict__ outF,
         __nv_bfloat16* __restrict__ qp, __nv_bfloat16* __restrict__ kp,
         __nv_bfloat16* __restrict__ vp)
{
    extern __shared__ __align__(1024) char smem[];
    const int tid  = threadIdx.x;
    const int lane = tid & 31;
    const int wid  = tid >> 5;
    const int warp_m = wid & 1;    // 2 x 64 rows
    const int warp_n = wid >> 1;   // 4 x 32 cols
    const int m0 = blockIdx.y * 128;
    const int n0 = blockIdx.x * 128;

    const uint32_t sbase = smem_u32(smem);
    const int qrow = lane & 15;
    const int qcol = lane >> 4;

    float acc[4][4][4];   // mi(4x16 rows) x ni(4x8 cols)
    #pragma unroll
    for (int a = 0; a < 4; a++)
        #pragma unroll
        for (int b = 0; b < 4; b++)
            #pragma unroll
            for (int c = 0; c < 4; c++) acc[a][b][c] = 0.f;

    gemm_cp(A, Bw, m0, n0, 0,  sbase,                     tid); cp_commit();
    gemm_cp(A, Bw, m0, n0, 32, sbase + (uint32_t)STAGE_B, tid); cp_commit();

    int buf_c = 0;
    int buf_i = 2;
    #pragma unroll 1
    for (int t = 0; t < GEMM_NT; t++) {
        asm volatile("cp.async.wait_group 1;" ::: "memory");
        __syncthreads();
        if (t + 2 < GEMM_NT)
            gemm_cp(A, Bw, m0, n0, (t + 2) * 32,
                    sbase + (uint32_t)buf_i * STAGE_B, tid);
        cp_commit();

        const uint32_t sAh = sbase + (uint32_t)buf_c * STAGE_B;
        const uint32_t sAl = sAh + 8192u;
        const uint32_t sBh = sAh + 16384u;
        const uint32_t sBl = sAh + 24576u;

        #pragma unroll
        for (int ks = 0; ks < 2; ks++) {
            uint32_t ah[4][4], al[4][4];
            #pragma unroll
            for (int mi = 0; mi < 4; mi++) {
                uint32_t off = (uint32_t)((warp_m * 64 + mi * 16 + qrow) * 64
                                          + (ks * 2 + qcol) * 16);
                off = swz64(off);
                ldsm4(ah[mi], sAh + off);
                ldsm4(al[mi], sAl + off);
            }
            #pragma unroll
            for (int nj = 0; nj < 2; nj++) {     // two 16-col blocks
                uint32_t bh[4], bl[4];
                uint32_t off = (uint32_t)((warp_n * 32 + nj * 16 + qrow) * 64
                                          + (ks * 2 + qcol) * 16);
                off = swz64(off);
                ldsm4(bh, sBh + off);
                ldsm4(bl, sBl + off);
                #pragma unroll
                for (int mi = 0; mi < 4; mi++)
                    #pragma unroll
                    for (int c2 = 0; c2 < 2; c2++) {
                        float* cc = acc[mi][nj * 2 + c2];
                        mma16816(cc, ah[mi], bh[c2], bh[2 + c2]);
                        mma16816(cc, al[mi], bh[c2], bh[2 + c2]);
                        mma16816(cc, ah[mi], bl[c2], bl[2 + c2]);
                    }
            }
        }

        buf_c = (buf_c == 2) ? 0 : buf_c + 1;
        buf_i = (buf_i == 2) ? 0 : buf_i + 1;
        __syncthreads();
    }

    const int tr = lane >> 2;
    const int tc = (lane & 3) * 2;
    const int which = n0 >> 10;                 // 0:Q 1:K 2:V (OMODE 1)
    const float scale = (OMODE == 1 && which == 0) ? 0.125f : 1.f;
    __nv_bfloat16* hdst = (which == 0) ? qp : (which == 1) ? kp : vp;
    const int ncol0 = n0 & 1023;

    #pragma unroll
    for (int mi = 0; mi < 4; mi++) {
        #pragma unroll
        for (int ni = 0; ni < 4; ni++) {
            const int row = m0 + warp_m * 64 + mi * 16 + tr;
            const int col = (OMODE ? ncol0 : n0) + warp_n * 32 + ni * 8 + tc;
            float* cc = acc[mi][ni];
            #pragma unroll
            for (int half = 0; half < 2; half++) {
                const int r = row + half * 8;
                float2 val = half ? make_float2(cc[2], cc[3]) : make_float2(cc[0], cc[1]);
                if (OMODE == 0) {
                    *(float2*)(outF + (size_t)r * ND + col) = val;
                } else {
                    val.x *= scale; val.y *= scale;
                    const int b = r >> 11, s = r & (NS - 1);
                    const int h = col >> 6, ch = col & 63;
                    __nv_bfloat162 hi = __floats2bfloat162_rn(val.x, val.y);
                    __nv_bfloat162 lo = __floats2bfloat162_rn(
                        val.x - __bfloat162float(hi.x), val.y - __bfloat162float(hi.y));
                    __nv_bfloat16* base = hdst
                        + (((size_t)(b * NH + h) * 2) * NS + s) * 64 + ch;
                    *(__nv_bfloat162*)base           = hi;
                    *(__nv_bfloat162*)(base + NS*64) = lo;
                }
            }
        }
    }
}

// ---------------------------------------------------------------------------
// HMMA causal flash attention (unchanged). CTA = (bh, 128 q-rows).
// Epilogue writes the 2-plane [hi | lo] A-operand rows for the Wo GEMM.
// ---------------------------------------------------------------------------
static constexpr int ATTN_SMEM = 32768 + 2 * 32768;  // 98304

__global__ void __launch_bounds__(128)
fattn(const __nv_bfloat16* __restrict__ Qg, const __nv_bfloat16* __restrict__ Kg,
      const __nv_bfloat16* __restrict__ Vg, __nv_bfloat16* __restrict__ As)
{
    extern __shared__ __align__(1024) char sm[];
    const uint32_t sb = smem_u32(sm);
    const int bh  = blockIdx.x;
    const int qt  = (int)gridDim.y - 1 - (int)blockIdx.y;
    const int tid = threadIdx.x, lane = tid & 31, w = tid >> 5;

    const __nv_bfloat16* Qbh = Qg + (size_t)bh * 2 * NS * 64;
    const __nv_bfloat16* Kbh = Kg + (size_t)bh * 2 * NS * 64;
    const __nv_bfloat16* Vbh = Vg + (size_t)bh * 2 * NS * 64;

    #pragma unroll
    for (int i = 0; i < 16; i++) {
        int c = tid + i * 128;
        int p = c >> 10, r = (c >> 3) & 127, col16 = c & 7;
        uint4 v = *(const uint4*)(Qbh + (size_t)p * NS * 64
                                  + (size_t)(qt * 128 + r) * 64 + col16 * 8);
        uint32_t off = (uint32_t)(r * 128 + col16 * 16);
        *(uint4*)(sm + p * 16384 + (off ^ ((off >> 3) & 0x70))) = v;
    }

    const int nkt = 2 * qt + 2;

    auto load_kv = [&](int kt, int buf) {
        const int kv0 = kt * 64;
        #pragma unroll
        for (int i = 0; i < 16; i++) {
            int c = tid + i * 128;
            int p = c >> 9;
            int r = (c >> 3) & 63, col16 = c & 7;
            const __nv_bfloat16* src = (p < 2 ? Kbh : Vbh)
                + (size_t)(p & 1) * NS * 64 + (size_t)(kv0 + r) * 64 + col16 * 8;
            uint32_t off = (uint32_t)(r * 128 + col16 * 16);
            cpasync16(sb + 32768 + buf * 32768 + p * 8192 + (off ^ ((off >> 3) & 0x70)), src);
        }
        cp_commit();
    };

    load_kv(0, 0);

    float m[2][2], l[2][2];
    #pragma unroll
    for (int a = 0; a < 2; a++)
        #pragma unroll
        for (int b = 0; b < 2; b++) { m[a][b] = -1e30f; l[a][b] = 0.f; }

    float o[2][8][4];
    #pragma unroll
    for (int a = 0; a < 2; a++)
        #pragma unroll
        for (int b = 0; b < 8; b++)
            #pragma unroll
            for (int c = 0; c < 4; c++) o[a][b][c] = 0.f;

    const int qw0 = qt * 128 + w * 32;
    const uint32_t qoff[3] = {0u, 16384u, 0u};
    const uint32_t koff[3] = {0u, 0u, 8192u};

    for (int kt = 0; kt < nkt; kt++) {
        if (kt + 1 < nkt) {
            load_kv(kt + 1, (kt + 1) & 1);
            asm volatile("cp.async.wait_group 1;" ::: "memory");
        } else {
            asm volatile("cp.async.wait_group 0;" ::: "memory");
        }
        __syncthreads();

        if (kt * 64 <= qw0 + 31) {
            const uint32_t sK = sb + 32768 + (uint32_t)(kt & 1) * 32768u;
            const uint32_t sV = sK + 16384u;

            float s_[2][8][4];
            #pragma unroll
            for (int a = 0; a < 2; a++)
                #pragma unroll
                for (int b = 0; b < 8; b++)
                    #pragma unroll
                    for (int c = 0; c < 4; c++) s_[a][b][c] = 0.f;

            #pragma unroll
            for (int ps = 0; ps < 3; ps++) {
                #pragma unroll
                for (int ks = 0; ks < 4; ks++) {
                    uint32_t a[2][4];
                    #pragma unroll
                    for (int mi = 0; mi < 2; mi++) {
                        uint32_t off = (uint32_t)((w * 32 + mi * 16 + (lane & 15)) * 128
                                                  + (ks * 2 + (lane >> 4)) * 16);
                        ldsm4(a[mi], sb + qoff[ps] + (off ^ ((off >> 3) & 0x70)));
                    }
                    uint32_t bb[4][4];
                    #pragma unroll
                    for (int nj = 0; nj < 4; nj++) {
                        uint32_t off = (uint32_t)((nj * 16 + (lane & 15)) * 128
                                                  + (ks * 2 + (lane >> 4)) * 16);
                        ldsm4(bb[nj], sK + koff[ps] + (off ^ ((off >> 3) & 0x70)));
                    }
                    #pragma unroll
                    for (int mi = 0; mi < 2; mi++)
                        #pragma unroll
                        for (int ni = 0; ni < 8; ni++)
                            mma16816(s_[mi][ni], a[mi],
                                     bb[ni >> 1][ni & 1], bb[ni >> 1][2 + (ni & 1)]);
                }
            }

            if (kt * 64 + 63 > qw0) {
                #pragma unroll
                for (int mi = 0; mi < 2; mi++)
                    #pragma unroll
                    for (int ni = 0; ni < 8; ni++)
                        #pragma unroll
                        for (int c = 0; c < 4; c++) {
                            int qr = qw0 + mi * 16 + ((c >> 1) << 3) + (lane >> 2);
                            int kc = kt * 64 + ni * 8 + ((lane & 3) << 1) + (c & 1);
                            if (kc > qr) s_[mi][ni][c] = -1e30f;
                        }
            }

            #pragma unroll
            for (int mi = 0; mi < 2; mi++)
                #pragma unroll
                for (int rh = 0; rh < 2; rh++) {
                    float mx = -1e30f;
                    #pragma unroll
                    for (int ni = 0; ni < 8; ni++)
                        mx = fmaxf(mx, fmaxf(s_[mi][ni][rh*2], s_[mi][ni][rh*2+1]));
                    mx = fmaxf(mx, __shfl_xor_sync(0xffffffffu, mx, 1));
                    mx = fmaxf(mx, __shfl_xor_sync(0xffffffffu, mx, 2));
                    float mn = fmaxf(m[mi][rh], mx);
                    float sc = __expf(m[mi][rh] - mn);
                    m[mi][rh] = mn;
                    float sum = 0.f;
                    #pragma unroll
                    for (int ni = 0; ni < 8; ni++) {
                        float p0 = __expf(s_[mi][ni][rh*2]   - mn);
                        float p1 = __expf(s_[mi][ni][rh*2+1] - mn);
                        s_[mi][ni][rh*2] = p0; s_[mi][ni][rh*2+1] = p1;
                        sum += p0 + p1;
                    }
                    sum += __shfl_xor_sync(0xffffffffu, sum, 1);
                    sum += __shfl_xor_sync(0xffffffffu, sum, 2);
                    l[mi][rh] = l[mi][rh] * sc + sum;
                    #pragma unroll
                    for (int ni = 0; ni < 8; ni++) {
                        o[mi][ni][rh*2]   *= sc;
                        o[mi][ni][rh*2+1] *= sc;
                    }
                }

            #pragma unroll
            for (int ks = 0; ks < 4; ks++) {
                uint32_t ah[2][4], al[2][4];
                #pragma unroll
                for (int mi = 0; mi < 2; mi++) {
                    const float* t0 = s_[mi][2*ks];
                    const float* t1 = s_[mi][2*ks+1];
                    ah[mi][0] = packbf(t0[0], t0[1]);
                    ah[mi][1] = packbf(t0[2], t0[3]);
                    ah[mi][2] = packbf(t1[0], t1[1]);
                    ah[mi][3] = packbf(t1[2], t1[3]);
                    al[mi][0] = packlo(t0[0], t0[1], ah[mi][0]);
                    al[mi][1] = packlo(t0[2], t0[3], ah[mi][1]);
                    al[mi][2] = packlo(t1[0], t1[1], ah[mi][2]);
                    al[mi][3] = packlo(t1[2], t1[3], ah[mi][3]);
                }
                uint32_t bvh[4][4], bvl[4][4];
                #pragma unroll
                for (int nj = 0; nj < 4; nj++) {
                    uint32_t off = (uint32_t)((ks * 16 + (lane & 15)) * 128
                                              + (nj * 2 + (lane >> 4)) * 16);
                    off ^= (off >> 3) & 0x70;
                    ldsm4t(bvh[nj], sV + off);
                    ldsm4t(bvl[nj], sV + 8192 + off);
                }
                #pragma unroll
                for (int mi = 0; mi < 2; mi++)
                    #pragma unroll
                    for (int nd = 0; nd < 8; nd++) {
                        uint32_t b0 = bvh[nd >> 1][(nd & 1) * 2];
                        uint32_t b1 = bvh[nd >> 1][(nd & 1) * 2 + 1];
                        mma16816(o[mi][nd], ah[mi], b0, b1);
                        mma16816(o[mi][nd], al[mi], b0, b1);
                        uint32_t c0 = bvl[nd >> 1][(nd & 1) * 2];
                        uint32_t c1 = bvl[nd >> 1][(nd & 1) * 2 + 1];
                        mma16816(o[mi][nd], ah[mi], c0, c1);
                    }
            }
        }
        __syncthreads();
    }

    // epilogue: O/l -> 2-plane split rows [hi | lo] of Wo GEMM's A operand
    const int b = bh >> 4, h = bh & 15;
    #pragma unroll
    for (int mi = 0; mi < 2; mi++)
        #pragma unroll
        for (int rh = 0; rh < 2; rh++) {
            float invl = 1.f / l[mi][rh];
            int row = qw0 + mi * 16 + rh * 8 + (lane >> 2);
            __nv_bfloat16* rbase = As + (size_t)(b * NS + row) * KX2 + h * 64;
            #pragma unroll
            for (int ni = 0; ni < 8; ni++) {
                float vx = o[mi][ni][rh*2] * invl;
                float vy = o[mi][ni][rh*2+1] * invl;
                __nv_bfloat162 hi = __floats2bfloat162_rn(vx, vy);
                __nv_bfloat162 lo = __floats2bfloat162_rn(
                    vx - __bfloat162float(hi.x), vy - __bfloat162float(hi.y));
                __nv_bfloat16* dst = rbase + ni * 8 + ((lane & 3) << 1);
                *(__nv_bfloat162*)dst          = hi;
                *(__nv_bfloat162*)(dst + 1024) = lo;
            }
        }
}

// ---------------------------------------------------------------------------
extern "C" void kernel_launch(void* const* d_in, const int* in_sizes, int n_in,
                              void* d_out, int out_size)
{
    const float* x  = (const float*)d_in[0];
    const float* Wq = (const float*)d_in[1];
    const float* Wk = (const float*)d_in[2];
    const float* Wv = (const float*)d_in[3];
    const float* Wo = (const float*)d_in[4];
    float* out = (float*)d_out;

    __nv_bfloat16 *xs, *as, *wqkv, *wo, *q, *k, *v;
    cudaGetSymbolAddress((void**)&xs,   g_xs);
    cudaGetSymbolAddress((void**)&as,   g_as);
    cudaGetSymbolAddress((void**)&wqkv, g_wqkv);
    cudaGetSymbolAddress((void**)&wo,   g_wo);
    cudaGetSymbolAddress((void**)&q,    g_q);
    cudaGetSymbolAddress((void**)&k,    g_k);
    cudaGetSymbolAddress((void**)&v,    g_v);

    cudaFuncSetAttribute(gemm_mma<0>, cudaFuncAttributeMaxDynamicSharedMemorySize, GEMM_SMEM);
    cudaFuncSetAttribute(gemm_mma<1>, cudaFuncAttributeMaxDynamicSharedMemorySize, GEMM_SMEM);
    cudaFuncSetAttribute(fattn, cudaFuncAttributeMaxDynamicSharedMemorySize, ATTN_SMEM);

    split_act<<<MROWS * (ND/2) / 256, 256>>>(x, xs);
    split_w<<<dim3(ND * (ND/2) / 256, 4), 256>>>(Wq, Wk, Wv, Wo, wqkv, wo);

    // fused QKV projection: N = 3072
    gemm_mma<1><<<dim3(3 * ND / 128, MROWS / 128), 256, GEMM_SMEM>>>(
        xs, wqkv, nullptr, q, k, v);

    fattn<<<dim3(NB * NH, NS / 128), 128, ATTN_SMEM>>>(q, k, v, as);

    gemm_mma<0><<<dim3(ND / 128, MROWS / 128), 256, GEMM_SMEM>>>(
        as, wo, out, nullptr, nullptr, nullptr);
}

// round 9
// speedup vs baseline: 1.0466x; 1.0233x over previous
#include <cuda_runtime.h>
#include <cuda_bf16.h>
#include <cstdint>

#define NB 4
#define NS 2048
#define ND 1024
#define NH 16
#define DKH 64
#define MROWS (NB*NS)   // 8192
#define KX2 2048        // 2 physical planes [hi | lo] per row

// ---------------- scratch (__device__ globals; no allocation) ----------------
__device__ __nv_bfloat16 g_xs[(size_t)MROWS * KX2];    // x split    [hi|lo]
__device__ __nv_bfloat16 g_as[(size_t)MROWS * KX2];    // attn split [hi|lo]
__device__ __nv_bfloat16 g_wqkv[(size_t)3 * ND * KX2]; // Wq|Wk|Wv   [hi|lo]
__device__ __nv_bfloat16 g_wo[(size_t)ND * KX2];
// split-bf16 Q/K/V: [bh][plane(hi=0,lo=1)][S][64]
__device__ __nv_bfloat16 g_q[(size_t)NB*NH*2*NS*DKH];
__device__ __nv_bfloat16 g_k[(size_t)NB*NH*2*NS*DKH];
__device__ __nv_bfloat16 g_v[(size_t)NB*NH*2*NS*DKH];

// ---------------- helpers ----------------
__device__ __forceinline__ uint32_t smem_u32(const void* p) {
    uint32_t a;
    asm("{ .reg .u64 t; cvta.to.shared.u64 t, %1; cvt.u32.u64 %0, t; }" : "=r"(a) : "l"(p));
    return a;
}
__device__ __forceinline__ void ldsm4(uint32_t* r, uint32_t addr) {
    asm volatile("ldmatrix.sync.aligned.m8n8.x4.shared.b16 {%0,%1,%2,%3}, [%4];"
                 : "=r"(r[0]), "=r"(r[1]), "=r"(r[2]), "=r"(r[3]) : "r"(addr));
}
__device__ __forceinline__ void ldsm4t(uint32_t* r, uint32_t addr) {
    asm volatile("ldmatrix.sync.aligned.m8n8.x4.trans.shared.b16 {%0,%1,%2,%3}, [%4];"
                 : "=r"(r[0]), "=r"(r[1]), "=r"(r[2]), "=r"(r[3]) : "r"(addr));
}
// NOTE: non-volatile on purpose — pure register op; lets ptxas interleave
// MMAs with later LDSMs instead of freezing program order.
__device__ __forceinline__ void mma16816(float* c, const uint32_t* a, uint32_t b0, uint32_t b1) {
    asm("mma.sync.aligned.m16n8k16.row.col.f32.bf16.bf16.f32 "
        "{%0,%1,%2,%3}, {%4,%5,%6,%7}, {%8,%9}, {%0,%1,%2,%3};"
        : "+f"(c[0]), "+f"(c[1]), "+f"(c[2]), "+f"(c[3])
        : "r"(a[0]), "r"(a[1]), "r"(a[2]), "r"(a[3]), "r"(b0), "r"(b1));
}
__device__ __forceinline__ void cpasync16(uint32_t dst, const void* src) {
    asm volatile("cp.async.cg.shared.global [%0], [%1], 16;" :: "r"(dst), "l"(src));
}
__device__ __forceinline__ void cp_commit() {
    asm volatile("cp.async.commit_group;" ::: "memory");
}
__device__ __forceinline__ uint32_t packbf(float a, float b) {
    __nv_bfloat162 h = __floats2bfloat162_rn(a, b);
    return *(uint32_t*)&h;
}
__device__ __forceinline__ uint32_t packlo(float a, float b, uint32_t hbits) {
    __nv_bfloat162 h = *(__nv_bfloat162*)&hbits;
    return packbf(a - __bfloat162float(h.x), b - __bfloat162float(h.y));
}
__device__ __forceinline__ float ex2(float x) {
    float r; asm("ex2.approx.ftz.f32 %0, %1;" : "=f"(r) : "f"(x)); return r;
}

// ---------------- fp32 -> split-bf16 (2 planes per row: [hi | lo]) ----------
__global__ void split_act(const float* __restrict__ src, __nv_bfloat16* __restrict__ dst)
{
    int i = blockIdx.x * blockDim.x + threadIdx.x;
    int r  = i >> 9;
    int cp = i & 511;
    float2 v = *(const float2*)(src + (size_t)r * ND + cp * 2);
    __nv_bfloat162 hh = __floats2bfloat162_rn(v.x, v.y);
    __nv_bfloat162 ll = __floats2bfloat162_rn(v.x - __bfloat162float(hh.x),
                                              v.y - __bfloat162float(hh.y));
    __nv_bfloat162* d2 = (__nv_bfloat162*)(dst + (size_t)r * KX2) + cp;
    d2[0]   = hh;
    d2[512] = ll;
}
__global__ void split_w(const float* __restrict__ Wq, const float* __restrict__ Wk,
                        const float* __restrict__ Wv, const float* __restrict__ Wo,
                        __nv_bfloat16* __restrict__ wqkv, __nv_bfloat16* __restrict__ wo)
{
    int which = blockIdx.y;
    const float* src = (which == 0) ? Wq : (which == 1) ? Wk : (which == 2) ? Wv : Wo;
    __nv_bfloat16* dst = (which == 3) ? wo : wqkv + (size_t)which * ND * KX2;
    int i = blockIdx.x * blockDim.x + threadIdx.x;
    int r  = i >> 9;
    int cp = i & 511;
    float2 v = *(const float2*)(src + (size_t)r * ND + cp * 2);
    __nv_bfloat162 hh = __floats2bfloat162_rn(v.x, v.y);
    __nv_bfloat162 ll = __floats2bfloat162_rn(v.x - __bfloat162float(hh.x),
                                              v.y - __bfloat162float(hh.y));
    __nv_bfloat162* d2 = (__nv_bfloat162*)(dst + (size_t)r * KX2) + cp;
    d2[0]   = hh;
    d2[512] = ll;
}

// ---------------- HMMA split-bf16 NT GEMM (3-term, 2-plane) -----------------
// C = Ah*Bh^T + Al*Bh^T + Ah*Bl^T over true K=1024. CTA 128x128, BK=32,
// 256 thr = 8 warps (2m x 4n, 64x32 warp tiles), 3-stage cp.async, 1 sync/stage.
static constexpr int GEMM_NT   = 1024 / 32;  // 32 stages
static constexpr int STAGE_B   = 4 * 8192;   // 32768
static constexpr int GEMM_SMEM = 3 * STAGE_B;

// log2(e) folded into Q so attention uses raw ex2
#define QSCALE (0.125f * 1.4426950408889634f)

__device__ __forceinline__ uint32_t swz64(uint32_t off) {
    return off ^ ((off >> 3) & 0x30);
}

__device__ __forceinline__ void gemm_cp(const __nv_bfloat16* __restrict__ A,
                                        const __nv_bfloat16* __restrict__ Bw,
                                        int m0, int n0, int k0,
                                        uint32_t sbuf, int tid)
{
    #pragma unroll
    for (int i = 0; i < 8; i++) {
        int c = tid + i * 256;            // 0..2047 16B chunks
        int tile = c >> 9;                // 0:Ah 1:Al 2:Bh 3:Bl
        int cc = c & 511;
        int r = cc >> 2, col16 = cc & 3;
        const __nv_bfloat16* src = (tile < 2)
            ? A  + (size_t)(m0 + r) * KX2 + (tile & 1) * 1024 + k0 + col16 * 8
            : Bw + (size_t)(n0 + r) * KX2 + (tile & 1) * 1024 + k0 + col16 * 8;
        uint32_t off = (uint32_t)(r * 64 + col16 * 16);
        cpasync16(sbuf + tile * 8192u + swz64(off), src);
    }
}

template<int OMODE>   // 0: fp32 out [M,ND]; 1: merged QKV -> split head layout
__global__ void __launch_bounds__(256, 2)
gemm_mma(const __nv_bfloat16* __restrict__ A, const __nv_bfloat16* __restrict__ Bw,
         float* __restrict__ outF,
         __nv_bfloat16* __restrict__ qp, __nv_bfloat16* __restrict__ kp,
         __nv_bfloat16* __restrict__ vp)
{
    extern __shared__ __align__(1024) char smem[];
    const int tid  = threadIdx.x;
    const int lane = tid & 31;
    const int wid  = tid >> 5;
    const int warp_m = wid & 1;    // 2 x 64 rows
    const int warp_n = wid >> 1;   // 4 x 32 cols
    const int m0 = blockIdx.y * 128;
    const int n0 = blockIdx.x * 128;

    const uint32_t sbase = smem_u32(smem);
    const int qrow = lane & 15;
    const int qcol = lane >> 4;

    float acc[4][4][4];   // mi(4x16 rows) x ni(4x8 cols)
    #pragma unroll
    for (int a = 0; a < 4; a++)
        #pragma unroll
        for (int b = 0; b < 4; b++)
            #pragma unroll
            for (int c = 0; c < 4; c++) acc[a][b][c] = 0.f;

    gemm_cp(A, Bw, m0, n0, 0,  sbase,                     tid); cp_commit();
    gemm_cp(A, Bw, m0, n0, 32, sbase + (uint32_t)STAGE_B, tid); cp_commit();

    int buf_c = 0;
    int buf_i = 2;
    #pragma unroll 1
    for (int t = 0; t < GEMM_NT; t++) {
        asm volatile("cp.async.wait_group 1;" ::: "memory");
        __syncthreads();   // also orders: all warps done reading buf(t-1)
        if (t + 2 < GEMM_NT)
            gemm_cp(A, Bw, m0, n0, (t + 2) * 32,
                    sbase + (uint32_t)buf_i * STAGE_B, tid);
        cp_commit();

        const uint32_t sAh = sbase + (uint32_t)buf_c * STAGE_B;
        const uint32_t sAl = sAh + 8192u;
        const uint32_t sBh = sAh + 16384u;
        const uint32_t sBl = sAh + 24576u;

        #pragma unroll
        for (int ks = 0; ks < 2; ks++) {
            uint32_t ah[4][4], al[4][4];
            #pragma unroll
            for (int mi = 0; mi < 4; mi++) {
                uint32_t off = (uint32_t)((warp_m * 64 + mi * 16 + qrow) * 64
                                          + (ks * 2 + qcol) * 16);
                off = swz64(off);
                ldsm4(ah[mi], sAh + off);
                ldsm4(al[mi], sAl + off);
            }
            #pragma unroll
            for (int nj = 0; nj < 2; nj++) {     // two 16-col blocks
                uint32_t bh[4], bl[4];
                uint32_t off = (uint32_t)((warp_n * 32 + nj * 16 + qrow) * 64
                                          + (ks * 2 + qcol) * 16);
                off = swz64(off);
                ldsm4(bh, sBh + off);
                ldsm4(bl, sBl + off);
                #pragma unroll
                for (int mi = 0; mi < 4; mi++)
                    #pragma unroll
                    for (int c2 = 0; c2 < 2; c2++) {
                        float* cc = acc[mi][nj * 2 + c2];
                        mma16816(cc, ah[mi], bh[c2], bh[2 + c2]);
                        mma16816(cc, al[mi], bh[c2], bh[2 + c2]);
                        mma16816(cc, ah[mi], bl[c2], bl[2 + c2]);
                    }
            }
        }

        buf_c = (buf_c == 2) ? 0 : buf_c + 1;
        buf_i = (buf_i == 2) ? 0 : buf_i + 1;
        // no bottom sync: next iter's top sync provides the ordering
    }

    const int tr = lane >> 2;
    const int tc = (lane & 3) * 2;
    const int which = n0 >> 10;                 // 0:Q 1:K 2:V (OMODE 1)
    const float scale = (OMODE == 1 && which == 0) ? QSCALE : 1.f;
    __nv_bfloat16* hdst = (which == 0) ? qp : (which == 1) ? kp : vp;
    const int ncol0 = n0 & 1023;

    #pragma unroll
    for (int mi = 0; mi < 4; mi++) {
        #pragma unroll
        for (int ni = 0; ni < 4; ni++) {
            const int row = m0 + warp_m * 64 + mi * 16 + tr;
            const int col = (OMODE ? ncol0 : n0) + warp_n * 32 + ni * 8 + tc;
            float* cc = acc[mi][ni];
            #pragma unroll
            for (int half = 0; half < 2; half++) {
                const int r = row + half * 8;
                float2 val = half ? make_float2(cc[2], cc[3]) : make_float2(cc[0], cc[1]);
                if (OMODE == 0) {
                    *(float2*)(outF + (size_t)r * ND + col) = val;
                } else {
                    val.x *= scale; val.y *= scale;
                    const int b = r >> 11, s = r & (NS - 1);
                    const int h = col >> 6, ch = col & 63;
                    __nv_bfloat162 hi = __floats2bfloat162_rn(val.x, val.y);
                    __nv_bfloat162 lo = __floats2bfloat162_rn(
                        val.x - __bfloat162float(hi.x), val.y - __bfloat162float(hi.y));
                    __nv_bfloat16* base = hdst
                        + (((size_t)(b * NH + h) * 2) * NS + s) * 64 + ch;
                    *(__nv_bfloat162*)base           = hi;
                    *(__nv_bfloat162*)(base + NS*64) = lo;
                }
            }
        }
    }
}

// ---------------------------------------------------------------------------
// HMMA causal flash attention. CTA = (bh, 128 q-rows). 4 warps x 32 rows.
// Scores already in log2 domain (Q pre-scaled by 0.125*log2e) -> raw ex2.
// Single __syncthreads per kv tile. QK passes reordered (Qh*Kh, Ql*Kh, Qh*Kl)
// so K frags load once per plane: 12 LDSM per k-step instead of 18.
// ---------------------------------------------------------------------------
static constexpr int ATTN_SMEM = 32768 + 2 * 32768;  // 98304

__global__ void __launch_bounds__(128)
fattn(const __nv_bfloat16* __restrict__ Qg, const __nv_bfloat16* __restrict__ Kg,
      const __nv_bfloat16* __restrict__ Vg, __nv_bfloat16* __restrict__ As)
{
    extern __shared__ __align__(1024) char sm[];
    const uint32_t sb = smem_u32(sm);
    const int bh  = blockIdx.x;
    const int qt  = (int)gridDim.y - 1 - (int)blockIdx.y;
    const int tid = threadIdx.x, lane = tid & 31, w = tid >> 5;

    const __nv_bfloat16* Qbh = Qg + (size_t)bh * 2 * NS * 64;
    const __nv_bfloat16* Kbh = Kg + (size_t)bh * 2 * NS * 64;
    const __nv_bfloat16* Vbh = Vg + (size_t)bh * 2 * NS * 64;

    #pragma unroll
    for (int i = 0; i < 16; i++) {
        int c = tid + i * 128;
        int p = c >> 10, r = (c >> 3) & 127, col16 = c & 7;
        uint4 v = *(const uint4*)(Qbh + (size_t)p * NS * 64
                                  + (size_t)(qt * 128 + r) * 64 + col16 * 8);
        uint32_t off = (uint32_t)(r * 128 + col16 * 16);
        *(uint4*)(sm + p * 16384 + (off ^ ((off >> 3) & 0x70))) = v;
    }

    const int nkt = 2 * qt + 2;

    auto load_kv = [&](int kt, int buf) {
        const int kv0 = kt * 64;
        #pragma unroll
        for (int i = 0; i < 16; i++) {
            int c = tid + i * 128;
            int p = c >> 9;
            int r = (c >> 3) & 63, col16 = c & 7;
            const __nv_bfloat16* src = (p < 2 ? Kbh : Vbh)
                + (size_t)(p & 1) * NS * 64 + (size_t)(kv0 + r) * 64 + col16 * 8;
            uint32_t off = (uint32_t)(r * 128 + col16 * 16);
            cpasync16(sb + 32768 + buf * 32768 + p * 8192 + (off ^ ((off >> 3) & 0x70)), src);
        }
        cp_commit();
    };

    load_kv(0, 0);

    float m[2][2], l[2][2];
    #pragma unroll
    for (int a = 0; a < 2; a++)
        #pragma unroll
        for (int b = 0; b < 2; b++) { m[a][b] = -1e30f; l[a][b] = 0.f; }

    float o[2][8][4];
    #pragma unroll
    for (int a = 0; a < 2; a++)
        #pragma unroll
        for (int b = 0; b < 8; b++)
            #pragma unroll
            for (int c = 0; c < 4; c++) o[a][b][c] = 0.f;

    const int qw0 = qt * 128 + w * 32;

    for (int kt = 0; kt < nkt; kt++) {
        asm volatile("cp.async.wait_group 0;" ::: "memory");
        __syncthreads();   // all data visible; all warps done with buf(kt-1)
        if (kt + 1 < nkt)
            load_kv(kt + 1, (kt + 1) & 1);   // overlaps compute(kt)

        if (kt * 64 <= qw0 + 31) {
            const uint32_t sK = sb + 32768 + (uint32_t)(kt & 1) * 32768u;
            const uint32_t sV = sK + 16384u;

            float s_[2][8][4];
            #pragma unroll
            for (int a = 0; a < 2; a++)
                #pragma unroll
                for (int b = 0; b < 8; b++)
                    #pragma unroll
                    for (int c = 0; c < 4; c++) s_[a][b][c] = 0.f;

            // ---- S = Qh*Kh + Ql*Kh + Qh*Kl, K frags loaded once per plane ----
            #pragma unroll
            for (int ks = 0; ks < 4; ks++) {
                uint32_t ah[2][4], al[2][4], bb[4][4];
                #pragma unroll
                for (int mi = 0; mi < 2; mi++) {
                    uint32_t off = (uint32_t)((w * 32 + mi * 16 + (lane & 15)) * 128
                                              + (ks * 2 + (lane >> 4)) * 16);
                    off ^= (off >> 3) & 0x70;
                    ldsm4(ah[mi], sb + off);            // Q hi plane
                    ldsm4(al[mi], sb + 16384u + off);   // Q lo plane
                }
                #pragma unroll
                for (int nj = 0; nj < 4; nj++) {
                    uint32_t off = (uint32_t)((nj * 16 + (lane & 15)) * 128
                                              + (ks * 2 + (lane >> 4)) * 16);
                    off ^= (off >> 3) & 0x70;
                    ldsm4(bb[nj], sK + off);            // K hi
                }
                #pragma unroll
                for (int mi = 0; mi < 2; mi++)
                    #pragma unroll
                    for (int ni = 0; ni < 8; ni++)
                        mma16816(s_[mi][ni], ah[mi],
                                 bb[ni >> 1][ni & 1], bb[ni >> 1][2 + (ni & 1)]);
                #pragma unroll
                for (int mi = 0; mi < 2; mi++)
                    #pragma unroll
                    for (int ni = 0; ni < 8; ni++)
                        mma16816(s_[mi][ni], al[mi],
                                 bb[ni >> 1][ni & 1], bb[ni >> 1][2 + (ni & 1)]);
                #pragma unroll
                for (int nj = 0; nj < 4; nj++) {
                    uint32_t off = (uint32_t)((nj * 16 + (lane & 15)) * 128
                                              + (ks * 2 + (lane >> 4)) * 16);
                    off ^= (off >> 3) & 0x70;
                    ldsm4(bb[nj], sK + 8192u + off);    // K lo (reuse array)
                }
                #pragma unroll
                for (int mi = 0; mi < 2; mi++)
                    #pragma unroll
                    for (int ni = 0; ni < 8; ni++)
                        mma16816(s_[mi][ni], ah[mi],
                                 bb[ni >> 1][ni & 1], bb[ni >> 1][2 + (ni & 1)]);
            }

            if (kt * 64 + 63 > qw0) {
                #pragma unroll
                for (int mi = 0; mi < 2; mi++)
                    #pragma unroll
                    for (int ni = 0; ni < 8; ni++)
                        #pragma unroll
                        for (int c = 0; c < 4; c++) {
                            int qr = qw0 + mi * 16 + ((c >> 1) << 3) + (lane >> 2);
                            int kc = kt * 64 + ni * 8 + ((lane & 3) << 1) + (c & 1);
                            if (kc > qr) s_[mi][ni][c] = -1e30f;
                        }
            }

            // ---- online softmax in log2 domain ----
            #pragma unroll
            for (int mi = 0; mi < 2; mi++)
                #pragma unroll
                for (int rh = 0; rh < 2; rh++) {
                    float mx = -1e30f;
                    #pragma unroll
                    for (int ni = 0; ni < 8; ni++)
                        mx = fmaxf(mx, fmaxf(s_[mi][ni][rh*2], s_[mi][ni][rh*2+1]));
                    mx = fmaxf(mx, __shfl_xor_sync(0xffffffffu, mx, 1));
                    mx = fmaxf(mx, __shfl_xor_sync(0xffffffffu, mx, 2));
                    float mn = fmaxf(m[mi][rh], mx);
                    float sc = ex2(m[mi][rh] - mn);
                    m[mi][rh] = mn;
                    float sum = 0.f;
                    #pragma unroll
                    for (int ni = 0; ni < 8; ni++) {
                        float p0 = ex2(s_[mi][ni][rh*2]   - mn);
                        float p1 = ex2(s_[mi][ni][rh*2+1] - mn);
                        s_[mi][ni][rh*2] = p0; s_[mi][ni][rh*2+1] = p1;
                        sum += p0 + p1;
                    }
                    sum += __shfl_xor_sync(0xffffffffu, sum, 1);
                    sum += __shfl_xor_sync(0xffffffffu, sum, 2);
                    l[mi][rh] = l[mi][rh] * sc + sum;
                    #pragma unroll
                    for (int ni = 0; ni < 8; ni++) {
                        o[mi][ni][rh*2]   *= sc;
                        o[mi][ni][rh*2+1] *= sc;
                    }
                }

            // ---- O += P V (3 split passes) ----
            #pragma unroll
            for (int ks = 0; ks < 4; ks++) {
                uint32_t ah[2][4], al[2][4];
                #pragma unroll
                for (int mi = 0; mi < 2; mi++) {
                    const float* t0 = s_[mi][2*ks];
                    const float* t1 = s_[mi][2*ks+1];
                    ah[mi][0] = packbf(t0[0], t0[1]);
                    ah[mi][1] = packbf(t0[2], t0[3]);
                    ah[mi][2] = packbf(t1[0], t1[1]);
                    ah[mi][3] = packbf(t1[2], t1[3]);
                    al[mi][0] = packlo(t0[0], t0[1], ah[mi][0]);
                    al[mi][1] = packlo(t0[2], t0[3], ah[mi][1]);
                    al[mi][2] = packlo(t1[0], t1[1], ah[mi][2]);
                    al[mi][3] = packlo(t1[2], t1[3], ah[mi][3]);
                }
                uint32_t bvh[4][4], bvl[4][4];
                #pragma unroll
                for (int nj = 0; nj < 4; nj++) {
                    uint32_t off = (uint32_t)((ks * 16 + (lane & 15)) * 128
                                              + (nj * 2 + (lane >> 4)) * 16);
                    off ^= (off >> 3) & 0x70;
                    ldsm4t(bvh[nj], sV + off);
                    ldsm4t(bvl[nj], sV + 8192 + off);
                }
                #pragma unroll
                for (int mi = 0; mi < 2; mi++)
                    #pragma unroll
                    for (int nd = 0; nd < 8; nd++) {
                        uint32_t b0 = bvh[nd >> 1][(nd & 1) * 2];
                        uint32_t b1 = bvh[nd >> 1][(nd & 1) * 2 + 1];
                        mma16816(o[mi][nd], ah[mi], b0, b1);
                        mma16816(o[mi][nd], al[mi], b0, b1);
                        uint32_t c0 = bvl[nd >> 1][(nd & 1) * 2];
                        uint32_t c1 = bvl[nd >> 1][(nd & 1) * 2 + 1];
                        mma16816(o[mi][nd], ah[mi], c0, c1);
                    }
            }
        }
        // no bottom sync: next iter's top sync provides the ordering
    }

    // epilogue: O/l -> 2-plane split rows [hi | lo] of Wo GEMM's A operand
    const int b = bh >> 4, h = bh & 15;
    #pragma unroll
    for (int mi = 0; mi < 2; mi++)
        #pragma unroll
        for (int rh = 0; rh < 2; rh++) {
            float invl = 1.f / l[mi][rh];
            int row = qw0 + mi * 16 + rh * 8 + (lane >> 2);
            __nv_bfloat16* rbase = As + (size_t)(b * NS + row) * KX2 + h * 64;
            #pragma unroll
            for (int ni = 0; ni < 8; ni++) {
                float vx = o[mi][ni][rh*2] * invl;
                float vy = o[mi][ni][rh*2+1] * invl;
                __nv_bfloat162 hi = __floats2bfloat162_rn(vx, vy);
                __nv_bfloat162 lo = __floats2bfloat162_rn(
                    vx - __bfloat162float(hi.x), vy - __bfloat162float(hi.y));
                __nv_bfloat16* dst = rbase + ni * 8 + ((lane & 3) << 1);
                *(__nv_bfloat162*)dst          = hi;
                *(__nv_bfloat162*)(dst + 1024) = lo;
            }
        }
}

// ---------------------------------------------------------------------------
extern "C" void kernel_launch(void* const* d_in, const int* in_sizes, int n_in,
                              void* d_out, int out_size)
{
    const float* x  = (const float*)d_in[0];
    const float* Wq = (const float*)d_in[1];
    const float* Wk = (const float*)d_in[2];
    const float* Wv = (const float*)d_in[3];
    const float* Wo = (const float*)d_in[4];
    float* out = (float*)d_out;

    __nv_bfloat16 *xs, *as, *wqkv, *wo, *q, *k, *v;
    cudaGetSymbolAddress((void**)&xs,   g_xs);
    cudaGetSymbolAddress((void**)&as,   g_as);
    cudaGetSymbolAddress((void**)&wqkv, g_wqkv);
    cudaGetSymbolAddress((void**)&wo,   g_wo);
    cudaGetSymbolAddress((void**)&q,    g_q);
    cudaGetSymbolAddress((void**)&k,    g_k);
    cudaGetSymbolAddress((void**)&v,    g_v);

    cudaFuncSetAttribute(gemm_mma<0>, cudaFuncAttributeMaxDynamicSharedMemorySize, GEMM_SMEM);
    cudaFuncSetAttribute(gemm_mma<1>, cudaFuncAttributeMaxDynamicSharedMemorySize, GEMM_SMEM);
    cudaFuncSetAttribute(fattn, cudaFuncAttributeMaxDynamicSharedMemorySize, ATTN_SMEM);

    split_act<<<MROWS * (ND/2) / 256, 256>>>(x, xs);
    split_w<<<dim3(ND * (ND/2) / 256, 4), 256>>>(Wq, Wk, Wv, Wo, wqkv, wo);

    // fused QKV projection: N = 3072
    gemm_mma<1><<<dim3(3 * ND / 128, MROWS / 128), 256, GEMM_SMEM>>>(
        xs, wqkv, nullptr, q, k, v);

    fattn<<<dim3(NB * NH, NS / 128), 128, ATTN_SMEM>>>(q, k, v, as);

    gemm_mma<0><<<dim3(ND / 128, MROWS / 128), 256, GEMM_SMEM>>>(
        as, wo, out, nullptr, nullptr, nullptr);
}

// round 10
// speedup vs baseline: 1.4731x; 1.4076x over previous
#include <cuda_runtime.h>
#include <cuda_fp16.h>
#include <cstdint>

#define NB 4
#define NS 2048
#define ND 1024
#define NH 16
#define DKH 64
#define MROWS (NB*NS)   // 8192
#define KX2 2048        // activation rows: 2 fp16 planes [hi | lo]

// ---------------- scratch (__device__ globals; no allocation) ----------------
__device__ __half g_xs[(size_t)MROWS * KX2];     // x split    [hi|lo] fp16
__device__ __half g_as[(size_t)MROWS * KX2];     // attn split [hi|lo] fp16
__device__ __half g_wqkv[(size_t)3 * ND * ND];   // Wq|Wk|Wv fp16 (1 plane)
__device__ __half g_wo[(size_t)ND * ND];         // Wo fp16 (1 plane)
__device__ __half g_q[(size_t)NB*NH*2*NS*DKH];   // Q: [bh][plane2][S][64]
__device__ __half g_k[(size_t)NB*NH*NS*DKH];     // K: [bh][S][64] (1 plane)
__device__ __half g_v[(size_t)NB*NH*NS*DKH];     // V: [bh][S][64] (1 plane)

// ---------------- helpers ----------------
__device__ __forceinline__ uint32_t smem_u32(const void* p) {
    uint32_t a;
    asm("{ .reg .u64 t; cvta.to.shared.u64 t, %1; cvt.u32.u64 %0, t; }" : "=r"(a) : "l"(p));
    return a;
}
__device__ __forceinline__ void ldsm4(uint32_t* r, uint32_t addr) {
    asm volatile("ldmatrix.sync.aligned.m8n8.x4.shared.b16 {%0,%1,%2,%3}, [%4];"
                 : "=r"(r[0]), "=r"(r[1]), "=r"(r[2]), "=r"(r[3]) : "r"(addr));
}
__device__ __forceinline__ void ldsm4t(uint32_t* r, uint32_t addr) {
    asm volatile("ldmatrix.sync.aligned.m8n8.x4.trans.shared.b16 {%0,%1,%2,%3}, [%4];"
                 : "=r"(r[0]), "=r"(r[1]), "=r"(r[2]), "=r"(r[3]) : "r"(addr));
}
// fp16 MMA, non-volatile (pure register op; lets ptxas interleave)
__device__ __forceinline__ void mma16816(float* c, const uint32_t* a, uint32_t b0, uint32_t b1) {
    asm("mma.sync.aligned.m16n8k16.row.col.f32.f16.f16.f32 "
        "{%0,%1,%2,%3}, {%4,%5,%6,%7}, {%8,%9}, {%0,%1,%2,%3};"
        : "+f"(c[0]), "+f"(c[1]), "+f"(c[2]), "+f"(c[3])
        : "r"(a[0]), "r"(a[1]), "r"(a[2]), "r"(a[3]), "r"(b0), "r"(b1));
}
__device__ __forceinline__ void cpasync16(uint32_t dst, const void* src) {
    asm volatile("cp.async.cg.shared.global [%0], [%1], 16;" :: "r"(dst), "l"(src));
}
__device__ __forceinline__ void cp_commit() {
    asm volatile("cp.async.commit_group;" ::: "memory");
}
__device__ __forceinline__ uint32_t packhf(float a, float b) {
    __half2 h = __floats2half2_rn(a, b);
    return *(uint32_t*)&h;
}
__device__ __forceinline__ uint32_t packhlo(float a, float b, uint32_t hbits) {
    __half2 h = *(__half2*)&hbits;
    return packhf(a - __low2float(h), b - __high2float(h));
}
__device__ __forceinline__ float ex2(float x) {
    float r; asm("ex2.approx.ftz.f32 %0, %1;" : "=f"(r) : "f"(x)); return r;
}

// log2(e) folded into Q so attention uses raw ex2
#define QSCALE (0.125f * 1.4426950408889634f)

// ---------------- fp32 -> fp16 conversions ----------------
// activations: 2 planes [hi | lo], row length KX2
__global__ void split_act(const float* __restrict__ src, __half* __restrict__ dst)
{
    int i = blockIdx.x * blockDim.x + threadIdx.x;
    int r  = i >> 9;
    int cp = i & 511;
    float2 v = *(const float2*)(src + (size_t)r * ND + cp * 2);
    __half2 hh = __floats2half2_rn(v.x, v.y);
    __half2 ll = __floats2half2_rn(v.x - __low2float(hh), v.y - __high2float(hh));
    __half2* d2 = (__half2*)(dst + (size_t)r * KX2) + cp;
    d2[0]   = hh;
    d2[512] = ll;
}
// weights: single fp16 plane, row length ND
__global__ void split_w(const float* __restrict__ Wq, const float* __restrict__ Wk,
                        const float* __restrict__ Wv, const float* __restrict__ Wo,
                        __half* __restrict__ wqkv, __half* __restrict__ wo)
{
    int which = blockIdx.y;
    const float* src = (which == 0) ? Wq : (which == 1) ? Wk : (which == 2) ? Wv : Wo;
    __half* dst = (which == 3) ? wo : wqkv + (size_t)which * ND * ND;
    int i = blockIdx.x * blockDim.x + threadIdx.x;
    int r  = i >> 9;
    int cp = i & 511;
    float2 v = *(const float2*)(src + (size_t)r * ND + cp * 2);
    ((__half2*)(dst + (size_t)r * ND))[cp] = __floats2half2_rn(v.x, v.y);
}

// ---------------- HMMA fp16 NT GEMM: C = Ah*W^T + Al*W^T -------------------
// A: [M, 2048] 2-plane fp16; W: [N, 1024] fp16. CTA 128x128, BK=32,
// 256 thr = 8 warps (2m x 4n, 64x32 warp tiles), 4-stage cp.async.
// Stage = Ah,Al,W tiles of 128x32 fp16 (8KB each) = 24KB.
static constexpr int GEMM_NT   = 1024 / 32;  // 32 stages
static constexpr int STAGE_B   = 3 * 8192;   // 24576
static constexpr int GEMM_SMEM = 4 * STAGE_B;  // 98304

__device__ __forceinline__ uint32_t swz64(uint32_t off) {
    return off ^ ((off >> 3) & 0x30);
}

__device__ __forceinline__ void gemm_cp(const __half* __restrict__ A,
                                        const __half* __restrict__ Bw,
                                        int m0, int n0, int k0,
                                        uint32_t sbuf, int tid)
{
    #pragma unroll
    for (int i = 0; i < 6; i++) {
        int c = tid + i * 256;            // 0..1535 16B chunks
        int tile = c >> 9;                // 0:Ah 1:Al 2:W
        int cc = c & 511;
        int r = cc >> 2, col16 = cc & 3;
        const __half* src = (tile < 2)
            ? A  + (size_t)(m0 + r) * KX2 + tile * 1024 + k0 + col16 * 8
            : Bw + (size_t)(n0 + r) * ND + k0 + col16 * 8;
        uint32_t off = (uint32_t)(r * 64 + col16 * 16);
        cpasync16(sbuf + tile * 8192u + swz64(off), src);
    }
}

template<int OMODE>   // 0: fp32 out [M,ND]; 1: merged QKV -> head layouts
__global__ void __launch_bounds__(256, 2)
gemm_mma(const __half* __restrict__ A, const __half* __restrict__ Bw,
         float* __restrict__ outF,
         __half* __restrict__ qp, __half* __restrict__ kp, __half* __restrict__ vp)
{
    extern __shared__ __align__(1024) char smem[];
    const int tid  = threadIdx.x;
    const int lane = tid & 31;
    const int wid  = tid >> 5;
    const int warp_m = wid & 1;    // 2 x 64 rows
    const int warp_n = wid >> 1;   // 4 x 32 cols
    const int m0 = blockIdx.y * 128;
    const int n0 = blockIdx.x * 128;

    const uint32_t sbase = smem_u32(smem);
    const int qrow = lane & 15;
    const int qcol = lane >> 4;

    float acc[4][4][4];
    #pragma unroll
    for (int a = 0; a < 4; a++)
        #pragma unroll
        for (int b = 0; b < 4; b++)
            #pragma unroll
            for (int c = 0; c < 4; c++) acc[a][b][c] = 0.f;

    gemm_cp(A, Bw, m0, n0, 0,  sbase,                         tid); cp_commit();
    gemm_cp(A, Bw, m0, n0, 32, sbase + (uint32_t)STAGE_B,     tid); cp_commit();
    gemm_cp(A, Bw, m0, n0, 64, sbase + (uint32_t)2 * STAGE_B, tid); cp_commit();

    int buf_c = 0;
    int buf_i = 3;
    #pragma unroll 1
    for (int t = 0; t < GEMM_NT; t++) {
        asm volatile("cp.async.wait_group 2;" ::: "memory");
        __syncthreads();   // also orders: all warps done reading buf(t-1)
        if (t + 3 < GEMM_NT)
            gemm_cp(A, Bw, m0, n0, (t + 3) * 32,
                    sbase + (uint32_t)buf_i * STAGE_B, tid);
        cp_commit();

        const uint32_t sAh = sbase + (uint32_t)buf_c * STAGE_B;
        const uint32_t sAl = sAh + 8192u;
        const uint32_t sB  = sAh + 16384u;

        #pragma unroll
        for (int ks = 0; ks < 2; ks++) {
            uint32_t ah[4][4], al[4][4];
            #pragma unroll
            for (int mi = 0; mi < 4; mi++) {
                uint32_t off = (uint32_t)((warp_m * 64 + mi * 16 + qrow) * 64
                                          + (ks * 2 + qcol) * 16);
                off = swz64(off);
                ldsm4(ah[mi], sAh + off);
                ldsm4(al[mi], sAl + off);
            }
            #pragma unroll
            for (int nj = 0; nj < 2; nj++) {
                uint32_t bh[4];
                uint32_t off = (uint32_t)((warp_n * 32 + nj * 16 + qrow) * 64
                                          + (ks * 2 + qcol) * 16);
                off = swz64(off);
                ldsm4(bh, sB + off);
                #pragma unroll
                for (int mi = 0; mi < 4; mi++)
                    #pragma unroll
                    for (int c2 = 0; c2 < 2; c2++) {
                        float* cc = acc[mi][nj * 2 + c2];
                        mma16816(cc, ah[mi], bh[c2], bh[2 + c2]);
                        mma16816(cc, al[mi], bh[c2], bh[2 + c2]);
                    }
            }
        }

        buf_c = (buf_c + 1) & 3;
        buf_i = (buf_i + 1) & 3;
    }

    const int tr = lane >> 2;
    const int tc = (lane & 3) * 2;
    const int which = n0 >> 10;                 // 0:Q 1:K 2:V (OMODE 1)
    const float scale = (OMODE == 1 && which == 0) ? QSCALE : 1.f;
    const int ncol0 = n0 & 1023;

    #pragma unroll
    for (int mi = 0; mi < 4; mi++) {
        #pragma unroll
        for (int ni = 0; ni < 4; ni++) {
            const int row = m0 + warp_m * 64 + mi * 16 + tr;
            const int col = (OMODE ? ncol0 : n0) + warp_n * 32 + ni * 8 + tc;
            float* cc = acc[mi][ni];
            #pragma unroll
            for (int half = 0; half < 2; half++) {
                const int r = row + half * 8;
                float2 val = half ? make_float2(cc[2], cc[3]) : make_float2(cc[0], cc[1]);
                if (OMODE == 0) {
                    *(float2*)(outF + (size_t)r * ND + col) = val;
                } else {
                    val.x *= scale; val.y *= scale;
                    const int b = r >> 11, s = r & (NS - 1);
                    const int h = col >> 6, ch = col & 63;
                    if (which == 0) {   // Q: 2 fp16 planes
                        __half2 hi = __floats2half2_rn(val.x, val.y);
                        __half2 lo = __floats2half2_rn(val.x - __low2float(hi),
                                                       val.y - __high2float(hi));
                        __half* base = qp + (((size_t)(b * NH + h) * 2) * NS + s) * 64 + ch;
                        *(__half2*)base           = hi;
                        *(__half2*)(base + NS*64) = lo;
                    } else {            // K/V: single fp16 plane
                        __half* dst = ((which == 1) ? kp : vp)
                            + ((size_t)(b * NH + h) * NS + s) * 64 + ch;
                        *(__half2*)dst = __floats2half2_rn(val.x, val.y);
                    }
                }
            }
        }
    }
}

// ---------------------------------------------------------------------------
// HMMA fp16 causal flash attention. CTA = (bh, 128 q-rows). 4 warps x 32 rows.
// S = (Qh + Ql)*K16 (2 terms); softmax in log2 domain (ex2);
// O = (Ph + Pl)*V16 (2 terms). KV tiles of 64, double-buffered cp.async.
// smem: Q 2x16KB | 2 bufs x (K,V) 2x8KB = 65536.
// ---------------------------------------------------------------------------
static constexpr int ATTN_SMEM = 32768 + 2 * 16384;  // 65536

__global__ void __launch_bounds__(128)
fattn(const __half* __restrict__ Qg, const __half* __restrict__ Kg,
      const __half* __restrict__ Vg, __half* __restrict__ As)
{
    extern __shared__ __align__(1024) char sm[];
    const uint32_t sb = smem_u32(sm);
    const int bh  = blockIdx.x;
    const int qt  = (int)gridDim.y - 1 - (int)blockIdx.y;  // big tiles first
    const int tid = threadIdx.x, lane = tid & 31, w = tid >> 5;

    const __half* Qbh = Qg + (size_t)bh * 2 * NS * 64;
    const __half* Kbh = Kg + (size_t)bh * NS * 64;
    const __half* Vbh = Vg + (size_t)bh * NS * 64;

    // Q tile: 2 planes x 128 x 64 fp16, SW128 swizzle (128B rows)
    #pragma unroll
    for (int i = 0; i < 16; i++) {
        int c = tid + i * 128;
        int p = c >> 10, r = (c >> 3) & 127, col16 = c & 7;
        uint4 v = *(const uint4*)(Qbh + (size_t)p * NS * 64
                                  + (size_t)(qt * 128 + r) * 64 + col16 * 8);
        uint32_t off = (uint32_t)(r * 128 + col16 * 16);
        *(uint4*)(sm + p * 16384 + (off ^ ((off >> 3) & 0x70))) = v;
    }

    const int nkt = 2 * qt + 2;

    auto load_kv = [&](int kt, int buf) {
        const int kv0 = kt * 64;
        #pragma unroll
        for (int i = 0; i < 8; i++) {
            int c = tid + i * 128;         // 0..1023
            int p = c >> 9;                // 0:K 1:V
            int r = (c >> 3) & 63, col16 = c & 7;
            const __half* src = (p == 0 ? Kbh : Vbh)
                + (size_t)(kv0 + r) * 64 + col16 * 8;
            uint32_t off = (uint32_t)(r * 128 + col16 * 16);
            cpasync16(sb + 32768 + buf * 16384 + p * 8192 + (off ^ ((off >> 3) & 0x70)), src);
        }
        cp_commit();
    };

    load_kv(0, 0);

    float m[2][2], l[2][2];
    #pragma unroll
    for (int a = 0; a < 2; a++)
        #pragma unroll
        for (int b = 0; b < 2; b++) { m[a][b] = -1e30f; l[a][b] = 0.f; }

    float o[2][8][4];
    #pragma unroll
    for (int a = 0; a < 2; a++)
        #pragma unroll
        for (int b = 0; b < 8; b++)
            #pragma unroll
            for (int c = 0; c < 4; c++) o[a][b][c] = 0.f;

    const int qw0 = qt * 128 + w * 32;

    for (int kt = 0; kt < nkt; kt++) {
        asm volatile("cp.async.wait_group 0;" ::: "memory");
        __syncthreads();   // data visible; all warps done with buf(kt-1)
        if (kt + 1 < nkt)
            load_kv(kt + 1, (kt + 1) & 1);   // overlaps compute(kt)

        if (kt * 64 <= qw0 + 31) {
            const uint32_t sK = sb + 32768 + (uint32_t)(kt & 1) * 16384u;
            const uint32_t sV = sK + 8192u;

            float s_[2][8][4];
            #pragma unroll
            for (int a = 0; a < 2; a++)
                #pragma unroll
                for (int b = 0; b < 8; b++)
                    #pragma unroll
                    for (int c = 0; c < 4; c++) s_[a][b][c] = 0.f;

            // ---- S = (Qh + Ql) * K16 ----
            #pragma unroll
            for (int ks = 0; ks < 4; ks++) {
                uint32_t ah[2][4], al[2][4], bb[4][4];
                #pragma unroll
                for (int mi = 0; mi < 2; mi++) {
                    uint32_t off = (uint32_t)((w * 32 + mi * 16 + (lane & 15)) * 128
                                              + (ks * 2 + (lane >> 4)) * 16);
                    off ^= (off >> 3) & 0x70;
                    ldsm4(ah[mi], sb + off);            // Q hi
                    ldsm4(al[mi], sb + 16384u + off);   // Q lo
                }
                #pragma unroll
                for (int nj = 0; nj < 4; nj++) {
                    uint32_t off = (uint32_t)((nj * 16 + (lane & 15)) * 128
                                              + (ks * 2 + (lane >> 4)) * 16);
                    off ^= (off >> 3) & 0x70;
                    ldsm4(bb[nj], sK + off);
                }
                #pragma unroll
                for (int mi = 0; mi < 2; mi++)
                    #pragma unroll
                    for (int ni = 0; ni < 8; ni++)
                        mma16816(s_[mi][ni], ah[mi],
                                 bb[ni >> 1][ni & 1], bb[ni >> 1][2 + (ni & 1)]);
                #pragma unroll
                for (int mi = 0; mi < 2; mi++)
                    #pragma unroll
                    for (int ni = 0; ni < 8; ni++)
                        mma16816(s_[mi][ni], al[mi],
                                 bb[ni >> 1][ni & 1], bb[ni >> 1][2 + (ni & 1)]);
            }

            if (kt * 64 + 63 > qw0) {
                #pragma unroll
                for (int mi = 0; mi < 2; mi++)
                    #pragma unroll
                    for (int ni = 0; ni < 8; ni++)
                        #pragma unroll
                        for (int c = 0; c < 4; c++) {
                            int qr = qw0 + mi * 16 + ((c >> 1) << 3) + (lane >> 2);
                            int kc = kt * 64 + ni * 8 + ((lane & 3) << 1) + (c & 1);
                            if (kc > qr) s_[mi][ni][c] = -1e30f;
                        }
            }

            // ---- online softmax in log2 domain ----
            #pragma unroll
            for (int mi = 0; mi < 2; mi++)
                #pragma unroll
                for (int rh = 0; rh < 2; rh++) {
                    float mx = -1e30f;
                    #pragma unroll
                    for (int ni = 0; ni < 8; ni++)
                        mx = fmaxf(mx, fmaxf(s_[mi][ni][rh*2], s_[mi][ni][rh*2+1]));
                    mx = fmaxf(mx, __shfl_xor_sync(0xffffffffu, mx, 1));
                    mx = fmaxf(mx, __shfl_xor_sync(0xffffffffu, mx, 2));
                    float mn = fmaxf(m[mi][rh], mx);
                    float sc = ex2(m[mi][rh] - mn);
                    m[mi][rh] = mn;
                    float sum = 0.f;
                    #pragma unroll
                    for (int ni = 0; ni < 8; ni++) {
                        float p0 = ex2(s_[mi][ni][rh*2]   - mn);
                        float p1 = ex2(s_[mi][ni][rh*2+1] - mn);
                        s_[mi][ni][rh*2] = p0; s_[mi][ni][rh*2+1] = p1;
                        sum += p0 + p1;
                    }
                    sum += __shfl_xor_sync(0xffffffffu, sum, 1);
                    sum += __shfl_xor_sync(0xffffffffu, sum, 2);
                    l[mi][rh] = l[mi][rh] * sc + sum;
                    #pragma unroll
                    for (int ni = 0; ni < 8; ni++) {
                        o[mi][ni][rh*2]   *= sc;
                        o[mi][ni][rh*2+1] *= sc;
                    }
                }

            // ---- O += (Ph + Pl) * V16 ----
            #pragma unroll
            for (int ks = 0; ks < 4; ks++) {
                uint32_t ah[2][4], al[2][4];
                #pragma unroll
                for (int mi = 0; mi < 2; mi++) {
                    const float* t0 = s_[mi][2*ks];
                    const float* t1 = s_[mi][2*ks+1];
                    ah[mi][0] = packhf(t0[0], t0[1]);
                    ah[mi][1] = packhf(t0[2], t0[3]);
                    ah[mi][2] = packhf(t1[0], t1[1]);
                    ah[mi][3] = packhf(t1[2], t1[3]);
                    al[mi][0] = packhlo(t0[0], t0[1], ah[mi][0]);
                    al[mi][1] = packhlo(t0[2], t0[3], ah[mi][1]);
                    al[mi][2] = packhlo(t1[0], t1[1], ah[mi][2]);
                    al[mi][3] = packhlo(t1[2], t1[3], ah[mi][3]);
                }
                uint32_t bv[4][4];
                #pragma unroll
                for (int nj = 0; nj < 4; nj++) {
                    uint32_t off = (uint32_t)((ks * 16 + (lane & 15)) * 128
                                              + (nj * 2 + (lane >> 4)) * 16);
                    off ^= (off >> 3) & 0x70;
                    ldsm4t(bv[nj], sV + off);
                }
                #pragma unroll
                for (int mi = 0; mi < 2; mi++)
                    #pragma unroll
                    for (int nd = 0; nd < 8; nd++) {
                        uint32_t b0 = bv[nd >> 1][(nd & 1) * 2];
                        uint32_t b1 = bv[nd >> 1][(nd & 1) * 2 + 1];
                        mma16816(o[mi][nd], ah[mi], b0, b1);
                        mma16816(o[mi][nd], al[mi], b0, b1);
                    }
            }
        }
    }

    // epilogue: O/l -> 2-plane fp16 rows [hi | lo] of Wo GEMM's A operand
    const int b = bh >> 4, h = bh & 15;
    #pragma unroll
    for (int mi = 0; mi < 2; mi++)
        #pragma unroll
        for (int rh = 0; rh < 2; rh++) {
            float invl = 1.f / l[mi][rh];
            int row = qw0 + mi * 16 + rh * 8 + (lane >> 2);
            __half* rbase = As + (size_t)(b * NS + row) * KX2 + h * 64;
            #pragma unroll
            for (int ni = 0; ni < 8; ni++) {
                float vx = o[mi][ni][rh*2] * invl;
                float vy = o[mi][ni][rh*2+1] * invl;
                __half2 hi = __floats2half2_rn(vx, vy);
                __half2 lo = __floats2half2_rn(vx - __low2float(hi),
                                               vy - __high2float(hi));
                __half* dst = rbase + ni * 8 + ((lane & 3) << 1);
                *(__half2*)dst          = hi;
                *(__half2*)(dst + 1024) = lo;
            }
        }
}

// ---------------------------------------------------------------------------
extern "C" void kernel_launch(void* const* d_in, const int* in_sizes, int n_in,
                              void* d_out, int out_size)
{
    const float* x  = (const float*)d_in[0];
    const float* Wq = (const float*)d_in[1];
    const float* Wk = (const float*)d_in[2];
    const float* Wv = (const float*)d_in[3];
    const float* Wo = (const float*)d_in[4];
    float* out = (float*)d_out;

    __half *xs, *as, *wqkv, *wo, *q, *k, *v;
    cudaGetSymbolAddress((void**)&xs,   g_xs);
    cudaGetSymbolAddress((void**)&as,   g_as);
    cudaGetSymbolAddress((void**)&wqkv, g_wqkv);
    cudaGetSymbolAddress((void**)&wo,   g_wo);
    cudaGetSymbolAddress((void**)&q,    g_q);
    cudaGetSymbolAddress((void**)&k,    g_k);
    cudaGetSymbolAddress((void**)&v,    g_v);

    cudaFuncSetAttribute(gemm_mma<0>, cudaFuncAttributeMaxDynamicSharedMemorySize, GEMM_SMEM);
    cudaFuncSetAttribute(gemm_mma<1>, cudaFuncAttributeMaxDynamicSharedMemorySize, GEMM_SMEM);
    cudaFuncSetAttribute(fattn, cudaFuncAttributeMaxDynamicSharedMemorySize, ATTN_SMEM);

    split_act<<<MROWS * (ND/2) / 256, 256>>>(x, xs);
    split_w<<<dim3(ND * (ND/2) / 256, 4), 256>>>(Wq, Wk, Wv, Wo, wqkv, wo);

    // fused QKV projection: N = 3072
    gemm_mma<1><<<dim3(3 * ND / 128, MROWS / 128), 256, GEMM_SMEM>>>(
        xs, wqkv, nullptr, q, k, v);

    fattn<<<dim3(NB * NH, NS / 128), 128, ATTN_SMEM>>>(q, k, v, as);

    gemm_mma<0><<<dim3(ND / 128, MROWS / 128), 256, GEMM_SMEM>>>(
        as, wo, out, nullptr, nullptr, nullptr);
}